// round 2
// baseline (speedup 1.0000x reference)
#include <cuda_runtime.h>
#include <cuda_bf16.h>
#include <math.h>

// ============================================================================
// CrossAttention (XCA-style channel attention), fp32 SIMT pipeline.
//
//   K1: kv  = w_kv @ x       per batch  (M=768, N=4096, K=384)  -> g_kv
//   K2: q   = w_q  @ query   per batch  (M=384, N=4096, K=192)  -> g_q
//   K3: Gram S[b,h,c,d] = q_c . k_d  +  qss/kss row sum-squares
//   K4: attn = softmax(S * qn^-1 * kn^-1 * T); W_eff = w_proj_blk @ attn
//   K5: out = W_eff[b] @ v[b]          (M=384, N=4096, K=384)
//
// All scratch lives in __device__ globals referenced directly from device
// code — kernel_launch contains ONLY kernel launches (graph-capture safe).
// ============================================================================

#define B   16
#define C   384
#define QC  192
#define HD  8
#define DC  48
#define HW  4096

__device__ float g_kv [(long long)B * 768 * HW];   // k rows [0,384), v rows [384,768)
__device__ float g_q  [(long long)B * C   * HW];
__device__ float g_S  [B * HD * DC * DC];
__device__ float g_qss[B * C];
__device__ float g_kss[B * C];
__device__ float g_weff[(long long)B * C * C];

// ============================================================================
// SGEMM body: C[M,N] = A[M,K] @ B[K,N], row-major. 128x128 tile, BK=8,
// 8x8 per thread, 256 threads, register-prefetch double buffer.
// M%128==0, N%128==0, K%8==0 required (true at all call sites).
// ============================================================================
template<int M, int N, int K>
__device__ __forceinline__
void sgemm_body(const float* __restrict__ A, const float* __restrict__ Bm,
                float* __restrict__ Cm)
{
    __shared__ float As[2][8][128];
    __shared__ float Bs[2][8][128];

    const int tid = threadIdx.x;
    const int bm = blockIdx.y * 128;
    const int bn = blockIdx.x * 128;

    const int aRow = tid >> 1;          // 0..127
    const int aCol = (tid & 1) << 2;    // 0 or 4
    const int bRow = tid >> 5;          // 0..7
    const int bCol = (tid & 31) << 2;   // 0..124

    const int tx = tid & 15;
    const int ty = tid >> 4;

    const float* Aptr = A  + (bm + aRow) * K + aCol;
    const float* Bptr = Bm + bRow * N + bn + bCol;

    float4 a4 = *(const float4*)Aptr;
    float4 b4 = *(const float4*)Bptr;

    As[0][aCol + 0][aRow] = a4.x;
    As[0][aCol + 1][aRow] = a4.y;
    As[0][aCol + 2][aRow] = a4.z;
    As[0][aCol + 3][aRow] = a4.w;
    *(float4*)&Bs[0][bRow][bCol] = b4;
    __syncthreads();

    float acc[8][8];
    #pragma unroll
    for (int i = 0; i < 8; i++)
        #pragma unroll
        for (int j = 0; j < 8; j++) acc[i][j] = 0.f;

    constexpr int nk = K >> 3;
    #pragma unroll 1
    for (int t = 0; t < nk; ++t) {
        const int cur = t & 1;
        if (t + 1 < nk) {
            a4 = *(const float4*)(Aptr + (t + 1) * 8);
            b4 = *(const float4*)(Bptr + (t + 1) * 8 * N);
        }
        #pragma unroll
        for (int kk = 0; kk < 8; ++kk) {
            float ar[8], br[8];
            *(float4*)&ar[0] = *(const float4*)&As[cur][kk][ty * 8];
            *(float4*)&ar[4] = *(const float4*)&As[cur][kk][ty * 8 + 4];
            *(float4*)&br[0] = *(const float4*)&Bs[cur][kk][tx * 8];
            *(float4*)&br[4] = *(const float4*)&Bs[cur][kk][tx * 8 + 4];
            #pragma unroll
            for (int i = 0; i < 8; i++)
                #pragma unroll
                for (int j = 0; j < 8; j++)
                    acc[i][j] += ar[i] * br[j];
        }
        if (t + 1 < nk) {
            const int nxt = cur ^ 1;
            As[nxt][aCol + 0][aRow] = a4.x;
            As[nxt][aCol + 1][aRow] = a4.y;
            As[nxt][aCol + 2][aRow] = a4.z;
            As[nxt][aCol + 3][aRow] = a4.w;
            *(float4*)&Bs[nxt][bRow][bCol] = b4;
        }
        __syncthreads();
    }

    #pragma unroll
    for (int i = 0; i < 8; i++) {
        float* crow = Cm + (bm + ty * 8 + i) * N + bn + tx * 8;
        *(float4*)crow       = make_float4(acc[i][0], acc[i][1], acc[i][2], acc[i][3]);
        *(float4*)(crow + 4) = make_float4(acc[i][4], acc[i][5], acc[i][6], acc[i][7]);
    }
}

// ---- stage wrappers (scratch referenced directly; no symbol lookup on host)
__global__ __launch_bounds__(256, 2)
void k1_kv(const float* __restrict__ w_kv, const float* __restrict__ x)
{
    const long long z = blockIdx.z;
    sgemm_body<768, HW, C>(w_kv, x + z * C * HW, g_kv + z * 768 * HW);
}

__global__ __launch_bounds__(256, 2)
void k2_q(const float* __restrict__ w_q, const float* __restrict__ query)
{
    const long long z = blockIdx.z;
    sgemm_body<C, HW, QC>(w_q, query + z * QC * HW, g_q + z * C * HW);
}

__global__ __launch_bounds__(256, 2)
void k5_out(float* __restrict__ out)
{
    const long long z = blockIdx.z;
    sgemm_body<C, HW, C>(g_weff + z * C * C, g_kv + z * 768 * HW + (long long)C * HW,
                         out + z * C * HW);
}

// ============================================================================
// K3: per (b,h) Gram S[c,d] = sum_n q[c,n]*k[d,n] (48x48, n=4096) + row
// sum-squares for L2-norm folding. 128 blocks, 256 threads, 3x3 per thread.
// ============================================================================
__global__ __launch_bounds__(256)
void gram_kernel()
{
    const int bh = blockIdx.x;          // 0..127
    const int b = bh >> 3, h = bh & 7;
    const float* qb = g_q  + ((long long)b * C   + h * DC) * HW;
    const float* kb = g_kv + ((long long)b * 768 + h * DC) * HW;

    __shared__ float qs[DC][65];
    __shared__ float ks[DC][65];

    const int tid = threadIdx.x;
    const int tx = tid & 15, ty = tid >> 4;

    float acc[3][3] = {};
    float nrm = 0.f;

    for (int n0 = 0; n0 < HW; n0 += 64) {
        for (int idx = tid; idx < DC * 16; idx += 256) {
            const int c = idx >> 4, nq = (idx & 15) << 2;
            float4 v = *(const float4*)(qb + (long long)c * HW + n0 + nq);
            qs[c][nq + 0] = v.x; qs[c][nq + 1] = v.y; qs[c][nq + 2] = v.z; qs[c][nq + 3] = v.w;
            float4 w = *(const float4*)(kb + (long long)c * HW + n0 + nq);
            ks[c][nq + 0] = w.x; ks[c][nq + 1] = w.y; ks[c][nq + 2] = w.z; ks[c][nq + 3] = w.w;
        }
        __syncthreads();

        #pragma unroll 4
        for (int nn = 0; nn < 64; ++nn) {
            const float a0 = qs[ty * 3 + 0][nn];
            const float a1 = qs[ty * 3 + 1][nn];
            const float a2 = qs[ty * 3 + 2][nn];
            const float b0 = ks[tx * 3 + 0][nn];
            const float b1 = ks[tx * 3 + 1][nn];
            const float b2 = ks[tx * 3 + 2][nn];
            acc[0][0] += a0 * b0; acc[0][1] += a0 * b1; acc[0][2] += a0 * b2;
            acc[1][0] += a1 * b0; acc[1][1] += a1 * b1; acc[1][2] += a1 * b2;
            acc[2][0] += a2 * b0; acc[2][1] += a2 * b1; acc[2][2] += a2 * b2;
        }
        if (tid < 96) {
            const float* row = (tid < DC) ? &qs[tid][0] : &ks[tid - DC][0];
            #pragma unroll 8
            for (int nn = 0; nn < 64; ++nn) { const float v = row[nn]; nrm += v * v; }
        }
        __syncthreads();
    }

    float* Sb = g_S + (long long)bh * DC * DC;
    #pragma unroll
    for (int i = 0; i < 3; i++)
        #pragma unroll
        for (int j = 0; j < 3; j++)
            Sb[(ty * 3 + i) * DC + (tx * 3 + j)] = acc[i][j];

    if (tid < DC)            g_qss[b * C + h * DC + tid]      = nrm;
    else if (tid < 2 * DC)   g_kss[b * C + h * DC + tid - DC] = nrm;
}

// ============================================================================
// K4: per (b,h): attn = softmax_d( S[c,d]*qn[c]^-1*kn[d]^-1*T[h] );
//     W_eff[b][o][h*48+d] = sum_c w_proj[o][h*48+c] * attn[c][d]
// ============================================================================
__global__ __launch_bounds__(256)
void softmax_weff(const float* __restrict__ temp, const float* __restrict__ w_proj)
{
    const int bh = blockIdx.x;
    const int b = bh >> 3, h = bh & 7;
    __shared__ float attn[DC][49];
    __shared__ float kinv[DC];

    const int tid = threadIdx.x;
    const float T = temp[h];

    if (tid < DC)
        kinv[tid] = 1.f / fmaxf(sqrtf(g_kss[b * C + h * DC + tid]), 1e-12f);
    __syncthreads();

    if (tid < DC) {
        const int c = tid;
        const float qinv = 1.f / fmaxf(sqrtf(g_qss[b * C + h * DC + c]), 1e-12f);
        const float* Sr = g_S + (long long)bh * DC * DC + c * DC;
        float vals[DC];
        float m = -INFINITY;
        #pragma unroll
        for (int d = 0; d < DC; d++) {
            const float l = Sr[d] * qinv * kinv[d] * T;
            vals[d] = l;
            m = fmaxf(m, l);
        }
        float s = 0.f;
        #pragma unroll
        for (int d = 0; d < DC; d++) { const float e = expf(vals[d] - m); vals[d] = e; s += e; }
        const float inv = 1.f / s;
        #pragma unroll
        for (int d = 0; d < DC; d++) attn[c][d] = vals[d] * inv;
    }
    __syncthreads();

    float* W = g_weff + (long long)b * C * C;
    for (int idx = tid; idx < C * DC; idx += 256) {
        const int o = idx / DC, d = idx % DC;
        const float* wp = w_proj + (long long)o * C + h * DC;
        float s = 0.f;
        #pragma unroll
        for (int c = 0; c < DC; c++) s += wp[c] * attn[c][d];
        W[(long long)o * C + h * DC + d] = s;
    }
}

// ============================================================================
// launch — kernel launches ONLY (graph-capture safe, allocation-free)
// ============================================================================
extern "C" void kernel_launch(void* const* d_in, const int* in_sizes, int n_in,
                              void* d_out, int out_size)
{
    const float* x      = (const float*)d_in[0];  // [16,384,64,64]
    const float* query  = (const float*)d_in[1];  // [16,192,64,64]
    const float* w_kv   = (const float*)d_in[2];  // [768,384]
    const float* w_q    = (const float*)d_in[3];  // [384,192]
    const float* w_proj = (const float*)d_in[4];  // [384,384]
    const float* temp   = (const float*)d_in[5];  // [8,1,1]
    float* out = (float*)d_out;                   // [16,384,64,64]

    {   // K1: kv = w_kv @ x
        dim3 grid(HW / 128, 768 / 128, B);
        k1_kv<<<grid, 256>>>(w_kv, x);
    }
    {   // K2: q = w_q @ query
        dim3 grid(HW / 128, C / 128, B);
        k2_q<<<grid, 256>>>(w_q, query);
    }
    gram_kernel<<<B * HD, 256>>>();           // K3
    softmax_weff<<<B * HD, 256>>>(temp, w_proj); // K4
    {   // K5: out = W_eff @ v
        dim3 grid(HW / 128, C / 128, B);
        k5_out<<<grid, 256>>>(out);
    }
}

// round 5
// speedup vs baseline: 1.8280x; 1.8280x over previous
#include <cuda_runtime.h>
#include <cuda_bf16.h>
#include <math.h>
#include <cstdint>

// ============================================================================
// CrossAttention — mma.sync split-bf16 pipeline (sm_100 baseline PTX; the
// harness compiles PTX for sm_100 without the 'a' suffix, so tcgen05 is
// unavailable; mma.sync.m16n8k16 + ldmatrix are baseline and hit the HMMA
// tensor pipe).
//
//  K1: kv  = w_kv @ x      per batch (M=768, N=4096, K=384)   [mma.sync]
//  K2: q   = w_q  @ query  per batch (M=384, N=4096, K=192)   [mma.sync]
//  K3: Gram S = q.k^T per (b,h), 4-way split-n partials        [SIMT]
//  K4a: softmax (L2-norm folded) -> attn                       [SIMT]
//  K4b: W_eff = w_proj_blockdiag @ attn                        [SIMT]
//  K5: out = W_eff @ v     per batch (M=384, N=4096, K=384)    [mma.sync]
//
// Split-bf16: a = a_hi + a_lo (bf16 each); D += ah*bh + al*bh + ah*bl
// into fp32 accumulators -> ~1e-5 relative error.
// ============================================================================

#define B   16
#define C   384
#define QC  192
#define HD  8
#define DC  48
#define HW  4096

// ---------------- scratch -------------------------------------------------
__device__ float g_kv [(long long)B * 768 * HW];   // k rows [0,384), v rows [384,768)
__device__ float g_q  [(long long)B * C * HW];
__device__ float g_Sp  [4 * B * HD * DC * DC];
__device__ float g_qssp[4 * B * C];
__device__ float g_kssp[4 * B * C];
__device__ float g_attn[(long long)B * HD * DC * DC];
__device__ float g_weff[(long long)B * C * C];

// ---------------- helpers --------------------------------------------------
__device__ __forceinline__ uint32_t smem_u32(const void* p) {
    uint32_t a;
    asm("{ .reg .u64 t; cvta.to.shared.u64 t, %1; cvt.u32.u64 %0, t; }" : "=r"(a) : "l"(p));
    return a;
}
__device__ __forceinline__ void ldsm_x4(uint32_t& r0, uint32_t& r1, uint32_t& r2, uint32_t& r3,
                                        uint32_t addr) {
    asm volatile("ldmatrix.sync.aligned.m8n8.x4.shared.b16 {%0,%1,%2,%3}, [%4];"
                 : "=r"(r0), "=r"(r1), "=r"(r2), "=r"(r3) : "r"(addr));
}
__device__ __forceinline__ void ldsm_x4_t(uint32_t& r0, uint32_t& r1, uint32_t& r2, uint32_t& r3,
                                          uint32_t addr) {
    asm volatile("ldmatrix.sync.aligned.m8n8.x4.trans.shared.b16 {%0,%1,%2,%3}, [%4];"
                 : "=r"(r0), "=r"(r1), "=r"(r2), "=r"(r3) : "r"(addr));
}
__device__ __forceinline__ void mma16816(float* c, const uint32_t* a, const uint32_t* b) {
    asm volatile("mma.sync.aligned.m16n8k16.row.col.f32.bf16.bf16.f32 "
                 "{%0,%1,%2,%3}, {%4,%5,%6,%7}, {%8,%9}, {%0,%1,%2,%3};"
                 : "+f"(c[0]), "+f"(c[1]), "+f"(c[2]), "+f"(c[3])
                 : "r"(a[0]), "r"(a[1]), "r"(a[2]), "r"(a[3]), "r"(b[0]), "r"(b[1]));
}
__device__ __forceinline__ uint32_t pack2(__nv_bfloat16 a, __nv_bfloat16 b) {
    return (uint32_t)__bfloat16_as_ushort(a) | ((uint32_t)__bfloat16_as_ushort(b) << 16);
}
__device__ __forceinline__ void split2(float x, float y, uint32_t& hi, uint32_t& lo) {
    __nv_bfloat16 hx = __float2bfloat16_rn(x);
    __nv_bfloat16 hy = __float2bfloat16_rn(y);
    __nv_bfloat16 lx = __float2bfloat16_rn(x - __bfloat162float(hx));
    __nv_bfloat16 ly = __float2bfloat16_rn(y - __bfloat162float(hy));
    hi = pack2(hx, hy);
    lo = pack2(lx, ly);
}

// ---------------- GEMM geometry -------------------------------------------
// CTA 128x128, BK=32, 256 threads = 8 warps (2x4), warp tile 64x32.
// smem (bf16 elems):
//   sA[buf][p][m 128][k 40pad] : p-stride 5120, buf-stride 10240, total 20480
//   sB[buf][p][k  32][n 136pad]: p-stride 4352, buf-stride 8704,  total 17408
#define SA_P 5120
#define SA_BUF 10240
#define SA_TOT 20480
#define SB_P 4352
#define SB_BUF 8704
#define SMEM_BYTES ((SA_TOT + 2 * SB_BUF) * 2)

template<int KTOT>
__device__ __forceinline__
void gemm_body(const float* __restrict__ A, const float* __restrict__ Bg,
               float* __restrict__ Cg)
{
    extern __shared__ __nv_bfloat16 sm[];
    __nv_bfloat16* sA = sm;
    __nv_bfloat16* sB = sm + SA_TOT;

    const int tid  = threadIdx.x;
    const int wid  = tid >> 5;
    const int lane = tid & 31;
    const int bn   = blockIdx.x * 128;

    const int wm = (wid >> 2) * 64;
    const int wn = (wid & 3) * 32;

    // per-thread staging coords
    //  A: f = tid + 256q -> row=f>>3, kc=(f&7)*4     (128x32 fp32)
    //  B: f = tid + 256q -> row=f>>5, nc=(f&31)*4    (32x128 fp32)
    float4 ra[4], rb[4];

    #define LOAD_TILES(kt) do { \
        _Pragma("unroll") \
        for (int q = 0; q < 4; ++q) { \
            const int fa = tid + 256 * q; \
            ra[q] = *(const float4*)(A + (fa >> 3) * KTOT + (kt) * 32 + ((fa & 7) << 2)); \
            rb[q] = *(const float4*)(Bg + (long long)((kt) * 32 + (fa >> 5)) * HW + bn + ((fa & 31) << 2)); \
        } \
    } while (0)

    #define STORE_TILES(buf) do { \
        _Pragma("unroll") \
        for (int q = 0; q < 4; ++q) { \
            const int fa = tid + 256 * q; \
            uint32_t h0, l0, h1, l1; \
            split2(ra[q].x, ra[q].y, h0, l0); \
            split2(ra[q].z, ra[q].w, h1, l1); \
            { \
                const int m = fa >> 3, kc = (fa & 7) << 2; \
                uint32_t* dh = (uint32_t*)&sA[(buf) * SA_BUF + m * 40 + kc]; \
                uint32_t* dl = (uint32_t*)&sA[(buf) * SA_BUF + SA_P + m * 40 + kc]; \
                dh[0] = h0; dh[1] = h1; dl[0] = l0; dl[1] = l1; \
            } \
            split2(rb[q].x, rb[q].y, h0, l0); \
            split2(rb[q].z, rb[q].w, h1, l1); \
            { \
                const int k = fa >> 5, nc = (fa & 31) << 2; \
                uint32_t* dh = (uint32_t*)&sB[(buf) * SB_BUF + k * 136 + nc]; \
                uint32_t* dl = (uint32_t*)&sB[(buf) * SB_BUF + SB_P + k * 136 + nc]; \
                dh[0] = h0; dh[1] = h1; dl[0] = l0; dl[1] = l1; \
            } \
        } \
    } while (0)

    float acc[4][4][4];
    #pragma unroll
    for (int i = 0; i < 4; ++i)
        #pragma unroll
        for (int j = 0; j < 4; ++j)
            #pragma unroll
            for (int r = 0; r < 4; ++r) acc[i][j][r] = 0.f;

    const uint32_t sA_u = smem_u32(sA);
    const uint32_t sB_u = smem_u32(sB);
    const int sub = lane >> 3;      // 0..3 (ldmatrix matrix id)
    const int lr  = lane & 7;

    LOAD_TILES(0);
    STORE_TILES(0);
    __syncthreads();

    constexpr int NK = KTOT / 32;
    #pragma unroll 1
    for (int t = 0; t < NK; ++t) {
        if (t + 1 < NK) LOAD_TILES(t + 1);

        const int buf = t & 1;
        #pragma unroll
        for (int ks = 0; ks < 2; ++ks) {
            const int k0 = ks * 16;
            uint32_t ah[4][4], al[4][4], bh[2][4], bl[2][4];
            // A frags: matrices [m0k0][m8k0][m0k8][m8k8]
            //   lane addr: row = wm+16i + (sub&1)*8 + lr, col = k0 + (sub>>1)*8
            #pragma unroll
            for (int i = 0; i < 4; ++i) {
                const int row = wm + 16 * i + (sub & 1) * 8 + lr;
                const int col = k0 + (sub >> 1) * 8;
                const uint32_t ab = sA_u + (uint32_t)(buf * SA_BUF + row * 40 + col) * 2;
                ldsm_x4(ah[i][0], ah[i][1], ah[i][2], ah[i][3], ab);
                ldsm_x4(al[i][0], al[i][1], al[i][2], al[i][3], ab + SA_P * 2);
            }
            // B frags (trans): matrices [k0,n0][k8,n0][k0,n8][k8,n8]
            //   lane addr: krow = k0 + (sub&1)*8 + lr, ncol = wn+16jj + (sub>>1)*8
            #pragma unroll
            for (int jj = 0; jj < 2; ++jj) {
                const int krow = k0 + (sub & 1) * 8 + lr;
                const int ncol = wn + 16 * jj + (sub >> 1) * 8;
                const uint32_t bb = sB_u + (uint32_t)(buf * SB_BUF + krow * 136 + ncol) * 2;
                ldsm_x4_t(bh[jj][0], bh[jj][1], bh[jj][2], bh[jj][3], bb);
                ldsm_x4_t(bl[jj][0], bl[jj][1], bl[jj][2], bl[jj][3], bb + SB_P * 2);
            }
            #pragma unroll
            for (int i = 0; i < 4; ++i)
                #pragma unroll
                for (int j = 0; j < 4; ++j) {
                    const uint32_t* bf_hi = &bh[j >> 1][(j & 1) * 2];
                    mma16816(acc[i][j], ah[i], bf_hi);       // hi*hi
                    mma16816(acc[i][j], al[i], bf_hi);       // lo*hi
                    mma16816(acc[i][j], ah[i], &bl[j >> 1][(j & 1) * 2]); // hi*lo
                }
        }

        if (t + 1 < NK) STORE_TILES((t + 1) & 1);
        __syncthreads();
    }

    // epilogue: acc regs -> gmem fp32
    const int g  = lane >> 2;
    const int tq = lane & 3;
    #pragma unroll
    for (int i = 0; i < 4; ++i)
        #pragma unroll
        for (int half = 0; half < 2; ++half) {
            const int row = wm + 16 * i + g + 8 * half;
            float* dst = Cg + (long long)row * HW + bn + wn + 2 * tq;
            #pragma unroll
            for (int j = 0; j < 4; ++j)
                *(float2*)(dst + 8 * j) = make_float2(acc[i][j][2 * half],
                                                      acc[i][j][2 * half + 1]);
        }
    #undef LOAD_TILES
    #undef STORE_TILES
}

__global__ __launch_bounds__(256)
void k1_kernel(const float* __restrict__ w_kv, const float* __restrict__ x)
{
    const long long z = blockIdx.z;
    gemm_body<384>(w_kv + blockIdx.y * 128 * 384,
                   x + z * C * HW,
                   g_kv + z * 768 * HW + (long long)blockIdx.y * 128 * HW);
}
__global__ __launch_bounds__(256)
void k2_kernel(const float* __restrict__ w_q, const float* __restrict__ query)
{
    const long long z = blockIdx.z;
    gemm_body<192>(w_q + blockIdx.y * 128 * 192,
                   query + z * QC * HW,
                   g_q + z * C * HW + (long long)blockIdx.y * 128 * HW);
}
__global__ __launch_bounds__(256)
void k5_kernel(float* __restrict__ out)
{
    const long long z = blockIdx.z;
    gemm_body<384>(g_weff + z * C * C + (long long)blockIdx.y * 128 * C,
                   g_kv + z * 768 * HW + (long long)C * HW,
                   out + z * C * HW + (long long)blockIdx.y * 128 * HW);
}

// ---------------- K3: Gram partials (4-way split over n) -------------------
__global__ __launch_bounds__(256)
void gram_kernel()
{
    const int bh = blockIdx.x;          // 0..127
    const int nq = blockIdx.y;          // 0..3
    const int b = bh >> 3, h = bh & 7;
    const float* qb = g_q  + ((long long)b * C   + h * DC) * HW;
    const float* kb = g_kv + ((long long)b * 768 + h * DC) * HW;

    __shared__ float qs[DC][65];
    __shared__ float ks[DC][65];

    const int tid = threadIdx.x;
    const int tx = tid & 15, ty = tid >> 4;

    float acc[3][3] = {};
    float nrm = 0.f;

    const int nbeg = nq * (HW / 4), nend = nbeg + (HW / 4);
    for (int n0 = nbeg; n0 < nend; n0 += 64) {
        for (int idx = tid; idx < DC * 16; idx += 256) {
            const int c = idx >> 4, nn4 = (idx & 15) << 2;
            float4 v = *(const float4*)(qb + (long long)c * HW + n0 + nn4);
            qs[c][nn4 + 0] = v.x; qs[c][nn4 + 1] = v.y; qs[c][nn4 + 2] = v.z; qs[c][nn4 + 3] = v.w;
            float4 w = *(const float4*)(kb + (long long)c * HW + n0 + nn4);
            ks[c][nn4 + 0] = w.x; ks[c][nn4 + 1] = w.y; ks[c][nn4 + 2] = w.z; ks[c][nn4 + 3] = w.w;
        }
        __syncthreads();
        #pragma unroll 4
        for (int nn = 0; nn < 64; ++nn) {
            const float a0 = qs[ty * 3 + 0][nn];
            const float a1 = qs[ty * 3 + 1][nn];
            const float a2 = qs[ty * 3 + 2][nn];
            const float b0 = ks[tx * 3 + 0][nn];
            const float b1 = ks[tx * 3 + 1][nn];
            const float b2 = ks[tx * 3 + 2][nn];
            acc[0][0] += a0 * b0; acc[0][1] += a0 * b1; acc[0][2] += a0 * b2;
            acc[1][0] += a1 * b0; acc[1][1] += a1 * b1; acc[1][2] += a1 * b2;
            acc[2][0] += a2 * b0; acc[2][1] += a2 * b1; acc[2][2] += a2 * b2;
        }
        if (tid < 96) {
            const float* row = (tid < DC) ? &qs[tid][0] : &ks[tid - DC][0];
            #pragma unroll 8
            for (int nn = 0; nn < 64; ++nn) { const float v = row[nn]; nrm += v * v; }
        }
        __syncthreads();
    }

    float* Sb = g_Sp + ((long long)nq * (B * HD) + bh) * DC * DC;
    #pragma unroll
    for (int i = 0; i < 3; i++)
        #pragma unroll
        for (int j = 0; j < 3; j++)
            Sb[(ty * 3 + i) * DC + (tx * 3 + j)] = acc[i][j];

    if (tid < DC)          g_qssp[nq * B * C + b * C + h * DC + tid]      = nrm;
    else if (tid < 2 * DC) g_kssp[nq * B * C + b * C + h * DC + tid - DC] = nrm;
}

// ---------------- K4a: softmax with folded L2 norms ------------------------
__global__ __launch_bounds__(64)
void k4a_softmax(const float* __restrict__ temp)
{
    const int bh = blockIdx.x;
    const int b = bh >> 3, h = bh & 7;
    const int tid = threadIdx.x;
    __shared__ float kinv[DC];

    if (tid < DC) {
        float kss = 0.f;
        #pragma unroll
        for (int p = 0; p < 4; ++p) kss += g_kssp[p * B * C + b * C + h * DC + tid];
        kinv[tid] = 1.f / fmaxf(sqrtf(kss), 1e-12f);
    }
    __syncthreads();

    if (tid < DC) {
        const int c = tid;
        float qss = 0.f;
        #pragma unroll
        for (int p = 0; p < 4; ++p) qss += g_qssp[p * B * C + b * C + h * DC + c];
        const float qinv = 1.f / fmaxf(sqrtf(qss), 1e-12f);
        const float T = temp[h];
        float vals[DC];
        float m = -INFINITY;
        #pragma unroll
        for (int d = 0; d < DC; d++) {
            float s = 0.f;
            #pragma unroll
            for (int p = 0; p < 4; ++p)
                s += g_Sp[((long long)p * (B * HD) + bh) * DC * DC + c * DC + d];
            const float l = s * qinv * kinv[d] * T;
            vals[d] = l;
            m = fmaxf(m, l);
        }
        float ssum = 0.f;
        #pragma unroll
        for (int d = 0; d < DC; d++) { const float e = expf(vals[d] - m); vals[d] = e; ssum += e; }
        const float inv = 1.f / ssum;
        float* dst = g_attn + (long long)bh * DC * DC + c * DC;
        #pragma unroll
        for (int d = 0; d < DC; d++) dst[d] = vals[d] * inv;
    }
}

// ---------------- K4b: W_eff = w_proj blockdiag-times attn -----------------
__global__ __launch_bounds__(256)
void k4b_weff(const float* __restrict__ w_proj)
{
    const int og = blockIdx.x;   // 0..3, 96 output rows each
    const int b  = blockIdx.y;   // 0..15
    const int tid = threadIdx.x;
    __shared__ float attn_s[DC][DC + 1];
    __shared__ float w_s[96][DC];

    for (int h = 0; h < HD; ++h) {
        const float* a_src = g_attn + ((long long)(b * HD + h)) * DC * DC;
        for (int idx = tid; idx < DC * DC; idx += 256)
            attn_s[idx / DC][idx % DC] = a_src[idx];
        for (int idx = tid; idx < 96 * DC; idx += 256) {
            const int o = idx / DC, c = idx % DC;
            w_s[o][c] = w_proj[(long long)(og * 96 + o) * C + h * DC + c];
        }
        __syncthreads();
        for (int idx = tid; idx < 96 * DC; idx += 256) {
            const int o = idx / DC, d = idx % DC;
            float s = 0.f;
            #pragma unroll
            for (int c = 0; c < DC; ++c) s += w_s[o][c] * attn_s[c][d];
            g_weff[(long long)b * C * C + (long long)(og * 96 + o) * C + h * DC + d] = s;
        }
        __syncthreads();
    }
}

// ---------------- launch ---------------------------------------------------
extern "C" void kernel_launch(void* const* d_in, const int* in_sizes, int n_in,
                              void* d_out, int out_size)
{
    const float* x      = (const float*)d_in[0];
    const float* query  = (const float*)d_in[1];
    const float* w_kv   = (const float*)d_in[2];
    const float* w_q    = (const float*)d_in[3];
    const float* w_proj = (const float*)d_in[4];
    const float* temp   = (const float*)d_in[5];
    float* out = (float*)d_out;

    cudaFuncSetAttribute(k1_kernel, cudaFuncAttributeMaxDynamicSharedMemorySize, SMEM_BYTES);
    cudaFuncSetAttribute(k2_kernel, cudaFuncAttributeMaxDynamicSharedMemorySize, SMEM_BYTES);
    cudaFuncSetAttribute(k5_kernel, cudaFuncAttributeMaxDynamicSharedMemorySize, SMEM_BYTES);

    k1_kernel<<<dim3(HW / 128, 6, B), 256, SMEM_BYTES>>>(w_kv, x);
    k2_kernel<<<dim3(HW / 128, 3, B), 256, SMEM_BYTES>>>(w_q, query);
    gram_kernel<<<dim3(B * HD, 4), 256>>>();
    k4a_softmax<<<B * HD, 64>>>(temp);
    k4b_weff<<<dim3(4, B), 256>>>(w_proj);
    k5_kernel<<<dim3(HW / 128, 3, B), 256, SMEM_BYTES>>>(out);
}

// round 6
// speedup vs baseline: 1.9979x; 1.0929x over previous
#include <cuda_runtime.h>
#include <cuda_bf16.h>
#include <math.h>
#include <cstdint>

// ============================================================================
// CrossAttention — mma.sync split-bf16 with pre-split operands + cp.async.
//
//  conv: x,query,w_kv,w_q -> bf16 hi/lo planes                 [SIMT, once]
//  K1: kv = w_kv @ x   -> k,v stored as bf16 hi/lo             [mma.sync]
//  K2: q  = w_q @ query -> q stored as bf16 hi/lo              [mma.sync]
//  K3: Gram S = q.k^T (hi+lo reconstruct), 4-way split-n       [SIMT]
//  K4a: softmax (L2-norm folded)                               [SIMT]
//  K4b: W_eff = w_proj_blockdiag @ attn -> bf16 hi/lo          [SIMT]
//  K5: out = W_eff @ v  -> fp32                                [mma.sync]
//
// GEMM hot loop: 3-stage cp.async pipeline, ldsm, 3-term MMA
// (ah*bh + al*bh + ah*bl), fp32 accum.
// ============================================================================

#define B   16
#define C   384
#define QC  192
#define HD  8
#define DC  48
#define HW  4096

// ---------------- scratch (bf16 hi/lo planes) ------------------------------
__device__ __nv_bfloat16 g_xh [(long long)B * C * HW];
__device__ __nv_bfloat16 g_xl [(long long)B * C * HW];
__device__ __nv_bfloat16 g_yh [(long long)B * QC * HW];   // query planes
__device__ __nv_bfloat16 g_yl [(long long)B * QC * HW];
__device__ __nv_bfloat16 g_kvh[(long long)B * 768 * HW];  // k rows [0,384), v rows [384,768)
__device__ __nv_bfloat16 g_kvl[(long long)B * 768 * HW];
__device__ __nv_bfloat16 g_qh [(long long)B * C * HW];
__device__ __nv_bfloat16 g_ql [(long long)B * C * HW];
__device__ __nv_bfloat16 g_wkvh[768 * 384], g_wkvl[768 * 384];
__device__ __nv_bfloat16 g_wqh [384 * 192], g_wql [384 * 192];
__device__ __nv_bfloat16 g_weffh[(long long)B * C * C], g_weffl[(long long)B * C * C];
__device__ float g_Sp  [4 * B * HD * DC * DC];
__device__ float g_qssp[4 * B * C];
__device__ float g_kssp[4 * B * C];
__device__ float g_attn[(long long)B * HD * DC * DC];

// ---------------- helpers --------------------------------------------------
__device__ __forceinline__ uint32_t smem_u32(const void* p) {
    uint32_t a;
    asm("{ .reg .u64 t; cvta.to.shared.u64 t, %1; cvt.u32.u64 %0, t; }" : "=r"(a) : "l"(p));
    return a;
}
__device__ __forceinline__ void ldsm_x4(uint32_t& r0, uint32_t& r1, uint32_t& r2, uint32_t& r3,
                                        uint32_t addr) {
    asm volatile("ldmatrix.sync.aligned.m8n8.x4.shared.b16 {%0,%1,%2,%3}, [%4];"
                 : "=r"(r0), "=r"(r1), "=r"(r2), "=r"(r3) : "r"(addr));
}
__device__ __forceinline__ void ldsm_x4_t(uint32_t& r0, uint32_t& r1, uint32_t& r2, uint32_t& r3,
                                          uint32_t addr) {
    asm volatile("ldmatrix.sync.aligned.m8n8.x4.trans.shared.b16 {%0,%1,%2,%3}, [%4];"
                 : "=r"(r0), "=r"(r1), "=r"(r2), "=r"(r3) : "r"(addr));
}
__device__ __forceinline__ void mma16816(float* c, const uint32_t* a, const uint32_t* b) {
    asm volatile("mma.sync.aligned.m16n8k16.row.col.f32.bf16.bf16.f32 "
                 "{%0,%1,%2,%3}, {%4,%5,%6,%7}, {%8,%9}, {%0,%1,%2,%3};"
                 : "+f"(c[0]), "+f"(c[1]), "+f"(c[2]), "+f"(c[3])
                 : "r"(a[0]), "r"(a[1]), "r"(a[2]), "r"(a[3]), "r"(b[0]), "r"(b[1]));
}
#define CP16(dst, src) \
    asm volatile("cp.async.cg.shared.global [%0], [%1], 16;" :: "r"(dst), "l"(src))
#define CP_COMMIT() asm volatile("cp.async.commit_group;")
#define CP_WAIT1()  asm volatile("cp.async.wait_group 1;")

__device__ __forceinline__ uint32_t pack2(__nv_bfloat16 a, __nv_bfloat16 b) {
    return (uint32_t)__bfloat16_as_ushort(a) | ((uint32_t)__bfloat16_as_ushort(b) << 16);
}
__device__ __forceinline__ void split1(float x, __nv_bfloat16& h, __nv_bfloat16& l) {
    h = __float2bfloat16_rn(x);
    l = __float2bfloat16_rn(x - __bfloat162float(h));
}
__device__ __forceinline__ float4 load4_split(const __nv_bfloat16* hp,
                                              const __nv_bfloat16* lp, long long idx) {
    uint2 h = *(const uint2*)(hp + idx);
    uint2 l = *(const uint2*)(lp + idx);
    const __nv_bfloat162 h0 = *reinterpret_cast<__nv_bfloat162*>(&h.x);
    const __nv_bfloat162 h1 = *reinterpret_cast<__nv_bfloat162*>(&h.y);
    const __nv_bfloat162 l0 = *reinterpret_cast<__nv_bfloat162*>(&l.x);
    const __nv_bfloat162 l1 = *reinterpret_cast<__nv_bfloat162*>(&l.y);
    float4 r;
    r.x = __bfloat162float(h0.x) + __bfloat162float(l0.x);
    r.y = __bfloat162float(h0.y) + __bfloat162float(l0.y);
    r.z = __bfloat162float(h1.x) + __bfloat162float(l1.x);
    r.w = __bfloat162float(h1.y) + __bfloat162float(l1.y);
    return r;
}

// ---------------- conversion kernel ----------------------------------------
__global__ __launch_bounds__(256)
void conv_split(const float* __restrict__ src, __nv_bfloat16* __restrict__ hi,
                __nv_bfloat16* __restrict__ lo, int n4)
{
    const int i = blockIdx.x * 256 + threadIdx.x;
    if (i >= n4) return;
    float4 v = ((const float4*)src)[i];
    __nv_bfloat16 h0, h1, h2, h3, l0, l1, l2, l3;
    split1(v.x, h0, l0); split1(v.y, h1, l1);
    split1(v.z, h2, l2); split1(v.w, h3, l3);
    ((uint2*)hi)[i] = make_uint2(pack2(h0, h1), pack2(h2, h3));
    ((uint2*)lo)[i] = make_uint2(pack2(l0, l1), pack2(l2, l3));
}

// ---------------- GEMM geometry -------------------------------------------
// CTA 128x128, BK=32, 256 threads = 8 warps (2x4), warp tile 64x32.
// smem per stage (bytes):
//   A: hi plane 128 rows x 80B (40 bf16, padded) = 10240; hi+lo = 20480
//   B: hi plane  32 rows x 272B (136 bf16)       =  8704; hi+lo = 17408
#define SA_ROWB  80
#define SA_PLANE 10240
#define SB_ROWB  272
#define SB_PLANE 8704
#define ST_A     20480
#define STAGE_B  37888
#define NSTAGE   3
#define SMEM_BYTES (STAGE_B * NSTAGE)

template<int KTOT, bool SPLIT_OUT>
__device__ __forceinline__
void gemm_body(const __nv_bfloat16* __restrict__ Ahi, const __nv_bfloat16* __restrict__ Alo,
               const __nv_bfloat16* __restrict__ Bhi, const __nv_bfloat16* __restrict__ Blo,
               float* __restrict__ Cf,
               __nv_bfloat16* __restrict__ Chi, __nv_bfloat16* __restrict__ Clo)
{
    extern __shared__ char sm[];
    const uint32_t smem_u = smem_u32(sm);

    const int tid  = threadIdx.x;
    const int wid  = tid >> 5;
    const int lane = tid & 31;
    const int bn   = blockIdx.x * 128;
    const int wm = (wid >> 2) * 64;
    const int wn = (wid & 3) * 32;
    const int sub = lane >> 3;
    const int lr  = lane & 7;

    // per-thread cp.async coords (2 chunks per plane per operand)
    const int ca0 = tid << 1;
    const int arow0 = ca0 >> 2,  aco0 = ca0 & 3;
    const int arow1 = (ca0 + 1) >> 2, aco1 = (ca0 + 1) & 3;
    const int brow0 = ca0 >> 4,  bco0 = ca0 & 15;
    const int brow1 = (ca0 + 1) >> 4, bco1 = (ca0 + 1) & 15;

    #define ISSUE(s, kt) do { \
        const uint32_t sb = smem_u + (s) * STAGE_B; \
        const __nv_bfloat16* ga; uint32_t d; \
        ga = Ahi + arow0 * KTOT + (kt) * 32 + aco0 * 8; \
        d = sb + arow0 * SA_ROWB + aco0 * 16; \
        CP16(d, ga); CP16(d + SA_PLANE, ga + (Alo - Ahi)); \
        ga = Ahi + arow1 * KTOT + (kt) * 32 + aco1 * 8; \
        d = sb + arow1 * SA_ROWB + aco1 * 16; \
        CP16(d, ga); CP16(d + SA_PLANE, ga + (Alo - Ahi)); \
        ga = Bhi + (long long)((kt) * 32 + brow0) * HW + bn + bco0 * 8; \
        d = sb + ST_A + brow0 * SB_ROWB + bco0 * 16; \
        CP16(d, ga); CP16(d + SB_PLANE, ga + (Blo - Bhi)); \
        ga = Bhi + (long long)((kt) * 32 + brow1) * HW + bn + bco1 * 8; \
        d = sb + ST_A + brow1 * SB_ROWB + bco1 * 16; \
        CP16(d, ga); CP16(d + SB_PLANE, ga + (Blo - Bhi)); \
    } while (0)

    float acc[4][4][4];
    #pragma unroll
    for (int i = 0; i < 4; ++i)
        #pragma unroll
        for (int j = 0; j < 4; ++j)
            #pragma unroll
            for (int r = 0; r < 4; ++r) acc[i][j][r] = 0.f;

    constexpr int NK = KTOT / 32;
    ISSUE(0, 0); CP_COMMIT();
    ISSUE(1, 1); CP_COMMIT();

    int s = 0;
    #pragma unroll 1
    for (int t = 0; t < NK; ++t) {
        CP_WAIT1();
        __syncthreads();

        if (t + 2 < NK) {
            int s2 = s + 2; if (s2 >= NSTAGE) s2 -= NSTAGE;
            ISSUE(s2, t + 2);
        }
        CP_COMMIT();

        const uint32_t aB = smem_u + s * STAGE_B;
        const uint32_t bB = aB + ST_A;
        #pragma unroll
        for (int ks = 0; ks < 2; ++ks) {
            const int k0 = ks * 16;
            uint32_t ah[4][4], al[4][4], bh[2][4], bl[2][4];
            #pragma unroll
            for (int i = 0; i < 4; ++i) {
                const int row = wm + 16 * i + (sub & 1) * 8 + lr;
                const int col = k0 + (sub >> 1) * 8;
                const uint32_t ab = aB + (uint32_t)row * SA_ROWB + (uint32_t)col * 2;
                ldsm_x4(ah[i][0], ah[i][1], ah[i][2], ah[i][3], ab);
                ldsm_x4(al[i][0], al[i][1], al[i][2], al[i][3], ab + SA_PLANE);
            }
            #pragma unroll
            for (int jj = 0; jj < 2; ++jj) {
                const int krow = k0 + (sub & 1) * 8 + lr;
                const int ncol = wn + 16 * jj + (sub >> 1) * 8;
                const uint32_t bb = bB + (uint32_t)krow * SB_ROWB + (uint32_t)ncol * 2;
                ldsm_x4_t(bh[jj][0], bh[jj][1], bh[jj][2], bh[jj][3], bb);
                ldsm_x4_t(bl[jj][0], bl[jj][1], bl[jj][2], bl[jj][3], bb + SB_PLANE);
            }
            #pragma unroll
            for (int i = 0; i < 4; ++i)
                #pragma unroll
                for (int j = 0; j < 4; ++j) {
                    const uint32_t* bfh = &bh[j >> 1][(j & 1) * 2];
                    mma16816(acc[i][j], ah[i], bfh);                       // hi*hi
                    mma16816(acc[i][j], al[i], bfh);                       // lo*hi
                    mma16816(acc[i][j], ah[i], &bl[j >> 1][(j & 1) * 2]);  // hi*lo
                }
        }
        if (++s >= NSTAGE) s -= NSTAGE;
    }

    // epilogue
    const int g  = lane >> 2;
    const int tq = lane & 3;
    #pragma unroll
    for (int i = 0; i < 4; ++i)
        #pragma unroll
        for (int half = 0; half < 2; ++half) {
            const int row = wm + 16 * i + g + 8 * half;
            const long long rb = (long long)row * HW + bn + wn + 2 * tq;
            #pragma unroll
            for (int j = 0; j < 4; ++j) {
                const float v0 = acc[i][j][2 * half];
                const float v1 = acc[i][j][2 * half + 1];
                if constexpr (SPLIT_OUT) {
                    __nv_bfloat16 h0, h1, l0, l1;
                    split1(v0, h0, l0); split1(v1, h1, l1);
                    *(uint32_t*)(Chi + rb + 8 * j) = pack2(h0, h1);
                    *(uint32_t*)(Clo + rb + 8 * j) = pack2(l0, l1);
                } else {
                    *(float2*)(Cf + rb + 8 * j) = make_float2(v0, v1);
                }
            }
        }
    #undef ISSUE
}

__global__ __launch_bounds__(256)
void k1_kernel()
{
    const long long z = blockIdx.z;
    const long long my = blockIdx.y;
    gemm_body<384, true>(g_wkvh + my * 128 * 384, g_wkvl + my * 128 * 384,
                         g_xh + z * C * HW, g_xl + z * C * HW,
                         nullptr,
                         g_kvh + z * 768 * HW + my * 128 * HW,
                         g_kvl + z * 768 * HW + my * 128 * HW);
}
__global__ __launch_bounds__(256)
void k2_kernel()
{
    const long long z = blockIdx.z;
    const long long my = blockIdx.y;
    gemm_body<192, true>(g_wqh + my * 128 * 192, g_wql + my * 128 * 192,
                         g_yh + z * QC * HW, g_yl + z * QC * HW,
                         nullptr,
                         g_qh + z * C * HW + my * 128 * HW,
                         g_ql + z * C * HW + my * 128 * HW);
}
__global__ __launch_bounds__(256)
void k5_kernel(float* __restrict__ out)
{
    const long long z = blockIdx.z;
    const long long my = blockIdx.y;
    gemm_body<384, false>(g_weffh + z * C * C + my * 128 * C,
                          g_weffl + z * C * C + my * 128 * C,
                          g_kvh + z * 768 * HW + (long long)C * HW,
                          g_kvl + z * 768 * HW + (long long)C * HW,
                          out + z * C * HW + my * 128 * HW,
                          nullptr, nullptr);
}

// ---------------- K3: Gram partials (4-way split over n) -------------------
__global__ __launch_bounds__(256)
void gram_kernel()
{
    const int bh = blockIdx.x;          // 0..127
    const int nq = blockIdx.y;          // 0..3
    const int b = bh >> 3, h = bh & 7;
    const long long qbase = ((long long)b * C   + h * DC) * HW;
    const long long kbase = ((long long)b * 768 + h * DC) * HW;

    __shared__ float qs[DC][65];
    __shared__ float ks[DC][65];

    const int tid = threadIdx.x;
    const int tx = tid & 15, ty = tid >> 4;

    float acc[3][3] = {};
    float nrm = 0.f;

    const int nbeg = nq * (HW / 4), nend = nbeg + (HW / 4);
    for (int n0 = nbeg; n0 < nend; n0 += 64) {
        for (int idx = tid; idx < DC * 16; idx += 256) {
            const int c = idx >> 4, nn4 = (idx & 15) << 2;
            float4 v = load4_split(g_qh, g_ql, qbase + (long long)c * HW + n0 + nn4);
            qs[c][nn4 + 0] = v.x; qs[c][nn4 + 1] = v.y; qs[c][nn4 + 2] = v.z; qs[c][nn4 + 3] = v.w;
            float4 w = load4_split(g_kvh, g_kvl, kbase + (long long)c * HW + n0 + nn4);
            ks[c][nn4 + 0] = w.x; ks[c][nn4 + 1] = w.y; ks[c][nn4 + 2] = w.z; ks[c][nn4 + 3] = w.w;
        }
        __syncthreads();
        #pragma unroll 4
        for (int nn = 0; nn < 64; ++nn) {
            const float a0 = qs[ty * 3 + 0][nn];
            const float a1 = qs[ty * 3 + 1][nn];
            const float a2 = qs[ty * 3 + 2][nn];
            const float b0 = ks[tx * 3 + 0][nn];
            const float b1 = ks[tx * 3 + 1][nn];
            const float b2 = ks[tx * 3 + 2][nn];
            acc[0][0] += a0 * b0; acc[0][1] += a0 * b1; acc[0][2] += a0 * b2;
            acc[1][0] += a1 * b0; acc[1][1] += a1 * b1; acc[1][2] += a1 * b2;
            acc[2][0] += a2 * b0; acc[2][1] += a2 * b1; acc[2][2] += a2 * b2;
        }
        if (tid < 96) {
            const float* row = (tid < DC) ? &qs[tid][0] : &ks[tid - DC][0];
            #pragma unroll 8
            for (int nn = 0; nn < 64; ++nn) { const float v = row[nn]; nrm += v * v; }
        }
        __syncthreads();
    }

    float* Sb = g_Sp + ((long long)nq * (B * HD) + bh) * DC * DC;
    #pragma unroll
    for (int i = 0; i < 3; i++)
        #pragma unroll
        for (int j = 0; j < 3; j++)
            Sb[(ty * 3 + i) * DC + (tx * 3 + j)] = acc[i][j];

    if (tid < DC)          g_qssp[nq * B * C + b * C + h * DC + tid]      = nrm;
    else if (tid < 2 * DC) g_kssp[nq * B * C + b * C + h * DC + tid - DC] = nrm;
}

// ---------------- K4a: softmax with folded L2 norms ------------------------
__global__ __launch_bounds__(64)
void k4a_softmax(const float* __restrict__ temp)
{
    const int bh = blockIdx.x;
    const int b = bh >> 3, h = bh & 7;
    const int tid = threadIdx.x;
    __shared__ float kinv[DC];

    if (tid < DC) {
        float kss = 0.f;
        #pragma unroll
        for (int p = 0; p < 4; ++p) kss += g_kssp[p * B * C + b * C + h * DC + tid];
        kinv[tid] = 1.f / fmaxf(sqrtf(kss), 1e-12f);
    }
    __syncthreads();

    if (tid < DC) {
        const int c = tid;
        float qss = 0.f;
        #pragma unroll
        for (int p = 0; p < 4; ++p) qss += g_qssp[p * B * C + b * C + h * DC + c];
        const float qinv = 1.f / fmaxf(sqrtf(qss), 1e-12f);
        const float T = temp[h];
        float vals[DC];
        float m = -INFINITY;
        #pragma unroll
        for (int d = 0; d < DC; d++) {
            float sv = 0.f;
            #pragma unroll
            for (int p = 0; p < 4; ++p)
                sv += g_Sp[((long long)p * (B * HD) + bh) * DC * DC + c * DC + d];
            const float l = sv * qinv * kinv[d] * T;
            vals[d] = l;
            m = fmaxf(m, l);
        }
        float ssum = 0.f;
        #pragma unroll
        for (int d = 0; d < DC; d++) { const float e = expf(vals[d] - m); vals[d] = e; ssum += e; }
        const float inv = 1.f / ssum;
        float* dst = g_attn + (long long)bh * DC * DC + c * DC;
        #pragma unroll
        for (int d = 0; d < DC; d++) dst[d] = vals[d] * inv;
    }
}

// ---------------- K4b: W_eff (split bf16 out) ------------------------------
__global__ __launch_bounds__(256)
void k4b_weff(const float* __restrict__ w_proj)
{
    const int og = blockIdx.x;   // 0..3, 96 output rows each
    const int b  = blockIdx.y;   // 0..15
    const int tid = threadIdx.x;
    __shared__ float attn_s[DC][DC + 1];
    __shared__ float w_s[96][DC];

    for (int h = 0; h < HD; ++h) {
        const float* a_src = g_attn + ((long long)(b * HD + h)) * DC * DC;
        for (int idx = tid; idx < DC * DC; idx += 256)
            attn_s[idx / DC][idx % DC] = a_src[idx];
        for (int idx = tid; idx < 96 * DC; idx += 256) {
            const int o = idx / DC, c = idx % DC;
            w_s[o][c] = w_proj[(long long)(og * 96 + o) * C + h * DC + c];
        }
        __syncthreads();
        for (int idx = tid; idx < 96 * DC; idx += 256) {
            const int o = idx / DC, d = idx % DC;
            float s = 0.f;
            #pragma unroll
            for (int c = 0; c < DC; ++c) s += w_s[o][c] * attn_s[c][d];
            const long long di = (long long)b * C * C + (long long)(og * 96 + o) * C + h * DC + d;
            __nv_bfloat16 hi, lo;
            split1(s, hi, lo);
            g_weffh[di] = hi;
            g_weffl[di] = lo;
        }
        __syncthreads();
    }
}

// ---------------- launch ---------------------------------------------------
extern "C" void kernel_launch(void* const* d_in, const int* in_sizes, int n_in,
                              void* d_out, int out_size)
{
    const float* x      = (const float*)d_in[0];
    const float* query  = (const float*)d_in[1];
    const float* w_kv   = (const float*)d_in[2];
    const float* w_q    = (const float*)d_in[3];
    const float* w_proj = (const float*)d_in[4];
    const float* temp   = (const float*)d_in[5];
    float* out = (float*)d_out;

    cudaFuncSetAttribute(k1_kernel, cudaFuncAttributeMaxDynamicSharedMemorySize, SMEM_BYTES);
    cudaFuncSetAttribute(k2_kernel, cudaFuncAttributeMaxDynamicSharedMemorySize, SMEM_BYTES);
    cudaFuncSetAttribute(k5_kernel, cudaFuncAttributeMaxDynamicSharedMemorySize, SMEM_BYTES);

    // conversions (counts are element_count/4)
    {
        __nv_bfloat16 *xh, *xl, *yh, *yl, *wkvh, *wkvl, *wqh, *wql;
        cudaGetSymbolAddress((void**)&xh, g_xh);   cudaGetSymbolAddress((void**)&xl, g_xl);
        cudaGetSymbolAddress((void**)&yh, g_yh);   cudaGetSymbolAddress((void**)&yl, g_yl);
        cudaGetSymbolAddress((void**)&wkvh, g_wkvh); cudaGetSymbolAddress((void**)&wkvl, g_wkvl);
        cudaGetSymbolAddress((void**)&wqh, g_wqh); cudaGetSymbolAddress((void**)&wql, g_wql);
        conv_split<<<(6291456 + 255) / 256, 256>>>(x, xh, xl, 6291456);
        conv_split<<<(3145728 + 255) / 256, 256>>>(query, yh, yl, 3145728);
        conv_split<<<(73728 + 255) / 256, 256>>>(w_kv, wkvh, wkvl, 73728);
        conv_split<<<(18432 + 255) / 256, 256>>>(w_q, wqh, wql, 18432);
    }

    k1_kernel<<<dim3(HW / 128, 6, B), 256, SMEM_BYTES>>>();
    k2_kernel<<<dim3(HW / 128, 3, B), 256, SMEM_BYTES>>>();
    gram_kernel<<<dim3(B * HD, 4), 256>>>();
    k4a_softmax<<<B * HD, 64>>>(temp);
    k4b_weff<<<dim3(4, B), 256>>>(w_proj);
    k5_kernel<<<dim3(HW / 128, 3, B), 256, SMEM_BYTES>>>(out);
}

// round 8
// speedup vs baseline: 2.3309x; 1.1667x over previous
#include <cuda_runtime.h>
#include <cuda_fp16.h>
#include <math.h>
#include <cstdint>

// ============================================================================
// CrossAttention — mma.sync fp16 2-term split pipeline.  (R8 = R7 resubmission;
// R7 died at the infra stage with the known broker-flake signature; kernel
// audited and unchanged.)
//
//  conv: w_kv,w_q -> fp16 hi/lo pairs; x,query -> fp16 hi only
//  K1: kv = w_kv(hi+lo) @ x(hi)   -> k,v stored fp16 hi/lo     [mma.sync]
//  K2: q  = w_q(hi+lo) @ query(hi) -> q stored fp16 hi/lo      [mma.sync]
//  K3: Gram S = q.k^T (hi+lo reconstruct), 4-way split-n       [SIMT]
//  K4a: softmax (L2-norm folded)                               [SIMT]
//  K4b: W_eff = w_proj_blockdiag @ attn -> fp16 hi/lo          [SIMT]
//  K5: out = W_eff(hi+lo) @ v(hi) -> fp32                      [mma.sync]
//
// 2-term: C = ah*bh + al*bh (A pair represents A to ~2^-22; B rounded once
// to fp16, dropped-term error ~2^-12 rel). MMA count -33% vs 3-term.
// ============================================================================

#define B   16
#define C   384
#define QC  192
#define HD  8
#define DC  48
#define HW  4096

// ---------------- scratch (fp16 planes) ------------------------------------
__device__ __half g_xh [(long long)B * C * HW];
__device__ __half g_yh [(long long)B * QC * HW];
__device__ __half g_kvh[(long long)B * 768 * HW];  // k rows [0,384), v rows [384,768)
__device__ __half g_kvl[(long long)B * 768 * HW];
__device__ __half g_qh [(long long)B * C * HW];
__device__ __half g_ql [(long long)B * C * HW];
__device__ __half g_wkvh[768 * 384], g_wkvl[768 * 384];
__device__ __half g_wqh [384 * 192], g_wql [384 * 192];
__device__ __half g_weffh[(long long)B * C * C], g_weffl[(long long)B * C * C];
__device__ float g_Sp  [4 * B * HD * DC * DC];
__device__ float g_qssp[4 * B * C];
__device__ float g_kssp[4 * B * C];
__device__ float g_attn[(long long)B * HD * DC * DC];

// ---------------- helpers --------------------------------------------------
__device__ __forceinline__ uint32_t smem_u32(const void* p) {
    uint32_t a;
    asm("{ .reg .u64 t; cvta.to.shared.u64 t, %1; cvt.u32.u64 %0, t; }" : "=r"(a) : "l"(p));
    return a;
}
__device__ __forceinline__ void ldsm_x4(uint32_t& r0, uint32_t& r1, uint32_t& r2, uint32_t& r3,
                                        uint32_t addr) {
    asm volatile("ldmatrix.sync.aligned.m8n8.x4.shared.b16 {%0,%1,%2,%3}, [%4];"
                 : "=r"(r0), "=r"(r1), "=r"(r2), "=r"(r3) : "r"(addr));
}
__device__ __forceinline__ void ldsm_x4_t(uint32_t& r0, uint32_t& r1, uint32_t& r2, uint32_t& r3,
                                          uint32_t addr) {
    asm volatile("ldmatrix.sync.aligned.m8n8.x4.trans.shared.b16 {%0,%1,%2,%3}, [%4];"
                 : "=r"(r0), "=r"(r1), "=r"(r2), "=r"(r3) : "r"(addr));
}
__device__ __forceinline__ void mma16816(float* c, const uint32_t* a, const uint32_t* b) {
    asm volatile("mma.sync.aligned.m16n8k16.row.col.f32.f16.f16.f32 "
                 "{%0,%1,%2,%3}, {%4,%5,%6,%7}, {%8,%9}, {%0,%1,%2,%3};"
                 : "+f"(c[0]), "+f"(c[1]), "+f"(c[2]), "+f"(c[3])
                 : "r"(a[0]), "r"(a[1]), "r"(a[2]), "r"(a[3]), "r"(b[0]), "r"(b[1]));
}
#define CP16(dst, src) \
    asm volatile("cp.async.cg.shared.global [%0], [%1], 16;" :: "r"(dst), "l"(src))
#define CP_COMMIT() asm volatile("cp.async.commit_group;")
#define CP_WAIT1()  asm volatile("cp.async.wait_group 1;")

__device__ __forceinline__ uint32_t pack2(__half a, __half b) {
    return (uint32_t)__half_as_ushort(a) | ((uint32_t)__half_as_ushort(b) << 16);
}
__device__ __forceinline__ void split1(float x, __half& h, __half& l) {
    h = __float2half_rn(x);
    l = __float2half_rn(x - __half2float(h));
}
__device__ __forceinline__ float4 load4_split(const __half* hp, const __half* lp,
                                              long long idx) {
    uint2 h = *(const uint2*)(hp + idx);
    uint2 l = *(const uint2*)(lp + idx);
    const __half2 h0 = *reinterpret_cast<__half2*>(&h.x);
    const __half2 h1 = *reinterpret_cast<__half2*>(&h.y);
    const __half2 l0 = *reinterpret_cast<__half2*>(&l.x);
    const __half2 l1 = *reinterpret_cast<__half2*>(&l.y);
    float4 r;
    r.x = __half2float(h0.x) + __half2float(l0.x);
    r.y = __half2float(h0.y) + __half2float(l0.y);
    r.z = __half2float(h1.x) + __half2float(l1.x);
    r.w = __half2float(h1.y) + __half2float(l1.y);
    return r;
}

// ---------------- conversion kernels ---------------------------------------
__global__ __launch_bounds__(256)
void conv_pair(const float* __restrict__ src, __half* __restrict__ hi,
               __half* __restrict__ lo, int n4)
{
    const int i = blockIdx.x * 256 + threadIdx.x;
    if (i >= n4) return;
    float4 v = ((const float4*)src)[i];
    __half h0, h1, h2, h3, l0, l1, l2, l3;
    split1(v.x, h0, l0); split1(v.y, h1, l1);
    split1(v.z, h2, l2); split1(v.w, h3, l3);
    ((uint2*)hi)[i] = make_uint2(pack2(h0, h1), pack2(h2, h3));
    ((uint2*)lo)[i] = make_uint2(pack2(l0, l1), pack2(l2, l3));
}
__global__ __launch_bounds__(256)
void conv_hi(const float* __restrict__ src, __half* __restrict__ hi, int n4)
{
    const int i = blockIdx.x * 256 + threadIdx.x;
    if (i >= n4) return;
    float4 v = ((const float4*)src)[i];
    ((uint2*)hi)[i] = make_uint2(pack2(__float2half_rn(v.x), __float2half_rn(v.y)),
                                 pack2(__float2half_rn(v.z), __float2half_rn(v.w)));
}

// ---------------- GEMM geometry -------------------------------------------
// CTA 128x128, BK=32, 256 threads = 8 warps (2x4), warp tile 64x32.
// smem per stage: A hi+lo planes (128 x 80B) = 20480 B; B hi plane
// (32 x 272B) = 8704 B; stage = 29184 B, 3 stages = 87552 B.
#define SA_ROWB  80
#define SA_PLANE 10240
#define SB_ROWB  272
#define SB_PLANE 8704
#define ST_A     20480
#define STAGE_B  29184
#define NSTAGE   3
#define SMEM_BYTES (STAGE_B * NSTAGE)

template<int KTOT, bool SPLIT_OUT>
__device__ __forceinline__
void gemm_body(const __half* __restrict__ Ahi, const __half* __restrict__ Alo,
               const __half* __restrict__ Bhi,
               float* __restrict__ Cf,
               __half* __restrict__ Chi, __half* __restrict__ Clo)
{
    extern __shared__ char sm[];
    const uint32_t smem_u = smem_u32(sm);

    const int tid  = threadIdx.x;
    const int wid  = tid >> 5;
    const int lane = tid & 31;
    const int bn   = blockIdx.x * 128;
    const int wm = (wid >> 2) * 64;
    const int wn = (wid & 3) * 32;
    const int sub = lane >> 3;
    const int lr  = lane & 7;

    const int ca0 = tid << 1;
    const int arow0 = ca0 >> 2,       aco0 = ca0 & 3;
    const int arow1 = (ca0 + 1) >> 2, aco1 = (ca0 + 1) & 3;
    const int brow0 = ca0 >> 4,       bco0 = ca0 & 15;
    const int brow1 = (ca0 + 1) >> 4, bco1 = (ca0 + 1) & 15;

    #define ISSUE(s, kt) do { \
        const uint32_t sb = smem_u + (s) * STAGE_B; \
        const __half* ga; uint32_t d; \
        ga = Ahi + arow0 * KTOT + (kt) * 32 + aco0 * 8; \
        d = sb + arow0 * SA_ROWB + aco0 * 16; \
        CP16(d, ga); CP16(d + SA_PLANE, ga + (Alo - Ahi)); \
        ga = Ahi + arow1 * KTOT + (kt) * 32 + aco1 * 8; \
        d = sb + arow1 * SA_ROWB + aco1 * 16; \
        CP16(d, ga); CP16(d + SA_PLANE, ga + (Alo - Ahi)); \
        ga = Bhi + (long long)((kt) * 32 + brow0) * HW + bn + bco0 * 8; \
        d = sb + ST_A + brow0 * SB_ROWB + bco0 * 16; \
        CP16(d, ga); \
        ga = Bhi + (long long)((kt) * 32 + brow1) * HW + bn + bco1 * 8; \
        d = sb + ST_A + brow1 * SB_ROWB + bco1 * 16; \
        CP16(d, ga); \
    } while (0)

    float acc[4][4][4];
    #pragma unroll
    for (int i = 0; i < 4; ++i)
        #pragma unroll
        for (int j = 0; j < 4; ++j)
            #pragma unroll
            for (int r = 0; r < 4; ++r) acc[i][j][r] = 0.f;

    constexpr int NK = KTOT / 32;
    ISSUE(0, 0); CP_COMMIT();
    ISSUE(1, 1); CP_COMMIT();

    int s = 0;
    #pragma unroll 1
    for (int t = 0; t < NK; ++t) {
        CP_WAIT1();
        __syncthreads();

        if (t + 2 < NK) {
            int s2 = s + 2; if (s2 >= NSTAGE) s2 -= NSTAGE;
            ISSUE(s2, t + 2);
        }
        CP_COMMIT();

        const uint32_t aB = smem_u + s * STAGE_B;
        const uint32_t bB = aB + ST_A;
        #pragma unroll
        for (int ks = 0; ks < 2; ++ks) {
            const int k0 = ks * 16;
            uint32_t ah[4][4], al[4][4], bh[2][4];
            #pragma unroll
            for (int i = 0; i < 4; ++i) {
                const int row = wm + 16 * i + (sub & 1) * 8 + lr;
                const int col = k0 + (sub >> 1) * 8;
                const uint32_t ab = aB + (uint32_t)row * SA_ROWB + (uint32_t)col * 2;
                ldsm_x4(ah[i][0], ah[i][1], ah[i][2], ah[i][3], ab);
                ldsm_x4(al[i][0], al[i][1], al[i][2], al[i][3], ab + SA_PLANE);
            }
            #pragma unroll
            for (int jj = 0; jj < 2; ++jj) {
                const int krow = k0 + (sub & 1) * 8 + lr;
                const int ncol = wn + 16 * jj + (sub >> 1) * 8;
                const uint32_t bb = bB + (uint32_t)krow * SB_ROWB + (uint32_t)ncol * 2;
                ldsm_x4_t(bh[jj][0], bh[jj][1], bh[jj][2], bh[jj][3], bb);
            }
            #pragma unroll
            for (int i = 0; i < 4; ++i)
                #pragma unroll
                for (int j = 0; j < 4; ++j) {
                    const uint32_t* bfh = &bh[j >> 1][(j & 1) * 2];
                    mma16816(acc[i][j], ah[i], bfh);   // hi*hi
                    mma16816(acc[i][j], al[i], bfh);   // lo*hi
                }
        }
        if (++s >= NSTAGE) s -= NSTAGE;
    }

    // epilogue
    const int g  = lane >> 2;
    const int tq = lane & 3;
    #pragma unroll
    for (int i = 0; i < 4; ++i)
        #pragma unroll
        for (int half = 0; half < 2; ++half) {
            const int row = wm + 16 * i + g + 8 * half;
            const long long rb = (long long)row * HW + bn + wn + 2 * tq;
            #pragma unroll
            for (int j = 0; j < 4; ++j) {
                const float v0 = acc[i][j][2 * half];
                const float v1 = acc[i][j][2 * half + 1];
                if constexpr (SPLIT_OUT) {
                    __half h0, h1, l0, l1;
                    split1(v0, h0, l0); split1(v1, h1, l1);
                    *(uint32_t*)(Chi + rb + 8 * j) = pack2(h0, h1);
                    *(uint32_t*)(Clo + rb + 8 * j) = pack2(l0, l1);
                } else {
                    *(float2*)(Cf + rb + 8 * j) = make_float2(v0, v1);
                }
            }
        }
    #undef ISSUE
}

__global__ __launch_bounds__(256)
void k1_kernel()
{
    const long long z = blockIdx.z;
    const long long my = blockIdx.y;
    gemm_body<384, true>(g_wkvh + my * 128 * 384, g_wkvl + my * 128 * 384,
                         g_xh + z * C * HW,
                         nullptr,
                         g_kvh + z * 768 * HW + my * 128 * HW,
                         g_kvl + z * 768 * HW + my * 128 * HW);
}
__global__ __launch_bounds__(256)
void k2_kernel()
{
    const long long z = blockIdx.z;
    const long long my = blockIdx.y;
    gemm_body<192, true>(g_wqh + my * 128 * 192, g_wql + my * 128 * 192,
                         g_yh + z * QC * HW,
                         nullptr,
                         g_qh + z * C * HW + my * 128 * HW,
                         g_ql + z * C * HW + my * 128 * HW);
}
__global__ __launch_bounds__(256)
void k5_kernel(float* __restrict__ out)
{
    const long long z = blockIdx.z;
    const long long my = blockIdx.y;
    gemm_body<384, false>(g_weffh + z * C * C + my * 128 * C,
                          g_weffl + z * C * C + my * 128 * C,
                          g_kvh + z * 768 * HW + (long long)C * HW,
                          out + z * C * HW + my * 128 * HW,
                          nullptr, nullptr);
}

// ---------------- K3: Gram partials (4-way split over n) -------------------
__global__ __launch_bounds__(256)
void gram_kernel()
{
    const int bh = blockIdx.x;          // 0..127
    const int nq = blockIdx.y;          // 0..3
    const int b = bh >> 3, h = bh & 7;
    const long long qbase = ((long long)b * C   + h * DC) * HW;
    const long long kbase = ((long long)b * 768 + h * DC) * HW;

    __shared__ float qs[DC][65];
    __shared__ float ks[DC][65];

    const int tid = threadIdx.x;
    const int tx = tid & 15, ty = tid >> 4;

    float acc[3][3] = {};
    float nrm = 0.f;

    const int nbeg = nq * (HW / 4), nend = nbeg + (HW / 4);
    for (int n0 = nbeg; n0 < nend; n0 += 64) {
        for (int idx = tid; idx < DC * 16; idx += 256) {
            const int c = idx >> 4, nn4 = (idx & 15) << 2;
            float4 v = load4_split(g_qh, g_ql, qbase + (long long)c * HW + n0 + nn4);
            qs[c][nn4 + 0] = v.x; qs[c][nn4 + 1] = v.y; qs[c][nn4 + 2] = v.z; qs[c][nn4 + 3] = v.w;
            float4 w = load4_split(g_kvh, g_kvl, kbase + (long long)c * HW + n0 + nn4);
            ks[c][nn4 + 0] = w.x; ks[c][nn4 + 1] = w.y; ks[c][nn4 + 2] = w.z; ks[c][nn4 + 3] = w.w;
        }
        __syncthreads();
        #pragma unroll 4
        for (int nn = 0; nn < 64; ++nn) {
            const float a0 = qs[ty * 3 + 0][nn];
            const float a1 = qs[ty * 3 + 1][nn];
            const float a2 = qs[ty * 3 + 2][nn];
            const float b0 = ks[tx * 3 + 0][nn];
            const float b1 = ks[tx * 3 + 1][nn];
            const float b2 = ks[tx * 3 + 2][nn];
            acc[0][0] += a0 * b0; acc[0][1] += a0 * b1; acc[0][2] += a0 * b2;
            acc[1][0] += a1 * b0; acc[1][1] += a1 * b1; acc[1][2] += a1 * b2;
            acc[2][0] += a2 * b0; acc[2][1] += a2 * b1; acc[2][2] += a2 * b2;
        }
        if (tid < 96) {
            const float* row = (tid < DC) ? &qs[tid][0] : &ks[tid - DC][0];
            #pragma unroll 8
            for (int nn = 0; nn < 64; ++nn) { const float v = row[nn]; nrm += v * v; }
        }
        __syncthreads();
    }

    float* Sb = g_Sp + ((long long)nq * (B * HD) + bh) * DC * DC;
    #pragma unroll
    for (int i = 0; i < 3; i++)
        #pragma unroll
        for (int j = 0; j < 3; j++)
            Sb[(ty * 3 + i) * DC + (tx * 3 + j)] = acc[i][j];

    if (tid < DC)          g_qssp[nq * B * C + b * C + h * DC + tid]      = nrm;
    else if (tid < 2 * DC) g_kssp[nq * B * C + b * C + h * DC + tid - DC] = nrm;
}

// ---------------- K4a: softmax with folded L2 norms ------------------------
__global__ __launch_bounds__(64)
void k4a_softmax(const float* __restrict__ temp)
{
    const int bh = blockIdx.x;
    const int b = bh >> 3, h = bh & 7;
    const int tid = threadIdx.x;
    __shared__ float kinv[DC];

    if (tid < DC) {
        float kss = 0.f;
        #pragma unroll
        for (int p = 0; p < 4; ++p) kss += g_kssp[p * B * C + b * C + h * DC + tid];
        kinv[tid] = 1.f / fmaxf(sqrtf(kss), 1e-12f);
    }
    __syncthreads();

    if (tid < DC) {
        const int c = tid;
        float qss = 0.f;
        #pragma unroll
        for (int p = 0; p < 4; ++p) qss += g_qssp[p * B * C + b * C + h * DC + c];
        const float qinv = 1.f / fmaxf(sqrtf(qss), 1e-12f);
        const float T = temp[h];
        float vals[DC];
        float m = -INFINITY;
        #pragma unroll
        for (int d = 0; d < DC; d++) {
            float sv = 0.f;
            #pragma unroll
            for (int p = 0; p < 4; ++p)
                sv += g_Sp[((long long)p * (B * HD) + bh) * DC * DC + c * DC + d];
            const float l = sv * qinv * kinv[d] * T;
            vals[d] = l;
            m = fmaxf(m, l);
        }
        float ssum = 0.f;
        #pragma unroll
        for (int d = 0; d < DC; d++) { const float e = expf(vals[d] - m); vals[d] = e; ssum += e; }
        const float inv = 1.f / ssum;
        float* dst = g_attn + (long long)bh * DC * DC + c * DC;
        #pragma unroll
        for (int d = 0; d < DC; d++) dst[d] = vals[d] * inv;
    }
}

// ---------------- K4b: W_eff (split fp16 out) ------------------------------
__global__ __launch_bounds__(256)
void k4b_weff(const float* __restrict__ w_proj)
{
    const int og = blockIdx.x;   // 0..3, 96 output rows each
    const int b  = blockIdx.y;   // 0..15
    const int tid = threadIdx.x;
    __shared__ float attn_s[DC][DC + 1];
    __shared__ float w_s[96][DC];

    for (int h = 0; h < HD; ++h) {
        const float* a_src = g_attn + ((long long)(b * HD + h)) * DC * DC;
        for (int idx = tid; idx < DC * DC; idx += 256)
            attn_s[idx / DC][idx % DC] = a_src[idx];
        for (int idx = tid; idx < 96 * DC; idx += 256) {
            const int o = idx / DC, c = idx % DC;
            w_s[o][c] = w_proj[(long long)(og * 96 + o) * C + h * DC + c];
        }
        __syncthreads();
        for (int idx = tid; idx < 96 * DC; idx += 256) {
            const int o = idx / DC, d = idx % DC;
            float s = 0.f;
            #pragma unroll
            for (int c = 0; c < DC; ++c) s += w_s[o][c] * attn_s[c][d];
            const long long di = (long long)b * C * C + (long long)(og * 96 + o) * C + h * DC + d;
            __half hi, lo;
            split1(s, hi, lo);
            g_weffh[di] = hi;
            g_weffl[di] = lo;
        }
        __syncthreads();
    }
}

// ---------------- launch ---------------------------------------------------
extern "C" void kernel_launch(void* const* d_in, const int* in_sizes, int n_in,
                              void* d_out, int out_size)
{
    const float* x      = (const float*)d_in[0];
    const float* query  = (const float*)d_in[1];
    const float* w_kv   = (const float*)d_in[2];
    const float* w_q    = (const float*)d_in[3];
    const float* w_proj = (const float*)d_in[4];
    const float* temp   = (const float*)d_in[5];
    float* out = (float*)d_out;

    cudaFuncSetAttribute(k1_kernel, cudaFuncAttributeMaxDynamicSharedMemorySize, SMEM_BYTES);
    cudaFuncSetAttribute(k2_kernel, cudaFuncAttributeMaxDynamicSharedMemorySize, SMEM_BYTES);
    cudaFuncSetAttribute(k5_kernel, cudaFuncAttributeMaxDynamicSharedMemorySize, SMEM_BYTES);

    {
        __half *xh, *yh, *wkvh, *wkvl, *wqh, *wql;
        cudaGetSymbolAddress((void**)&xh, g_xh);
        cudaGetSymbolAddress((void**)&yh, g_yh);
        cudaGetSymbolAddress((void**)&wkvh, g_wkvh); cudaGetSymbolAddress((void**)&wkvl, g_wkvl);
        cudaGetSymbolAddress((void**)&wqh, g_wqh);   cudaGetSymbolAddress((void**)&wql, g_wql);
        conv_hi<<<(6291456 + 255) / 256, 256>>>(x, xh, 6291456);
        conv_hi<<<(3145728 + 255) / 256, 256>>>(query, yh, 3145728);
        conv_pair<<<(73728 + 255) / 256, 256>>>(w_kv, wkvh, wkvl, 73728);
        conv_pair<<<(18432 + 255) / 256, 256>>>(w_q, wqh, wql, 18432);
    }

    k1_kernel<<<dim3(HW / 128, 6, B), 256, SMEM_BYTES>>>();
    k2_kernel<<<dim3(HW / 128, 3, B), 256, SMEM_BYTES>>>();
    gram_kernel<<<dim3(B * HD, 4), 256>>>();
    k4a_softmax<<<B * HD, 64>>>(temp);
    k4b_weff<<<dim3(4, B), 256>>>(w_proj);
    k5_kernel<<<dim3(HW / 128, 3, B), 256, SMEM_BYTES>>>(out);
}

// round 9
// speedup vs baseline: 2.3681x; 1.0160x over previous
#include <cuda_runtime.h>
#include <cuda_fp16.h>
#include <math.h>
#include <cstdint>

// ============================================================================
// CrossAttention — mma.sync fp16 2-term split pipeline, 2 CTAs/SM.
//
//  conv: w_kv,w_q -> fp16 hi/lo pairs; x,query -> fp16 hi only
//  K1: kv = w_kv(hi+lo) @ x(hi)   -> k,v stored fp16 hi/lo     [mma.sync]
//  K2: q  = w_q(hi+lo) @ query(hi) -> q stored fp16 hi/lo      [mma.sync]
//  K3: Gram S = q.k^T (hi+lo reconstruct), 4-way split-n       [SIMT]
//  K4a: softmax (L2-norm folded)                               [SIMT]
//  K4b: W_eff = w_proj_blockdiag @ attn -> fp16 hi/lo          [SIMT]
//  K5: out = W_eff(hi+lo) @ v(hi) -> fp32                      [mma.sync]
//
// R9 change: __launch_bounds__(256, 2) on GEMM kernels — 2 co-resident
// CTAs/SM (4 warps/SMSP) to hide barrier/cp.async/ldsm latency that R8
// analysis showed dominates (~550us non-MMA vs ~420us MMA).
// ============================================================================

#define B   16
#define C   384
#define QC  192
#define HD  8
#define DC  48
#define HW  4096

// ---------------- scratch (fp16 planes) ------------------------------------
__device__ __half g_xh [(long long)B * C * HW];
__device__ __half g_yh [(long long)B * QC * HW];
__device__ __half g_kvh[(long long)B * 768 * HW];  // k rows [0,384), v rows [384,768)
__device__ __half g_kvl[(long long)B * 768 * HW];
__device__ __half g_qh [(long long)B * C * HW];
__device__ __half g_ql [(long long)B * C * HW];
__device__ __half g_wkvh[768 * 384], g_wkvl[768 * 384];
__device__ __half g_wqh [384 * 192], g_wql [384 * 192];
__device__ __half g_weffh[(long long)B * C * C], g_weffl[(long long)B * C * C];
__device__ float g_Sp  [4 * B * HD * DC * DC];
__device__ float g_qssp[4 * B * C];
__device__ float g_kssp[4 * B * C];
__device__ float g_attn[(long long)B * HD * DC * DC];

// ---------------- helpers --------------------------------------------------
__device__ __forceinline__ uint32_t smem_u32(const void* p) {
    uint32_t a;
    asm("{ .reg .u64 t; cvta.to.shared.u64 t, %1; cvt.u32.u64 %0, t; }" : "=r"(a) : "l"(p));
    return a;
}
__device__ __forceinline__ void ldsm_x4(uint32_t& r0, uint32_t& r1, uint32_t& r2, uint32_t& r3,
                                        uint32_t addr) {
    asm volatile("ldmatrix.sync.aligned.m8n8.x4.shared.b16 {%0,%1,%2,%3}, [%4];"
                 : "=r"(r0), "=r"(r1), "=r"(r2), "=r"(r3) : "r"(addr));
}
__device__ __forceinline__ void ldsm_x4_t(uint32_t& r0, uint32_t& r1, uint32_t& r2, uint32_t& r3,
                                          uint32_t addr) {
    asm volatile("ldmatrix.sync.aligned.m8n8.x4.trans.shared.b16 {%0,%1,%2,%3}, [%4];"
                 : "=r"(r0), "=r"(r1), "=r"(r2), "=r"(r3) : "r"(addr));
}
__device__ __forceinline__ void mma16816(float* c, const uint32_t* a, const uint32_t* b) {
    asm volatile("mma.sync.aligned.m16n8k16.row.col.f32.f16.f16.f32 "
                 "{%0,%1,%2,%3}, {%4,%5,%6,%7}, {%8,%9}, {%0,%1,%2,%3};"
                 : "+f"(c[0]), "+f"(c[1]), "+f"(c[2]), "+f"(c[3])
                 : "r"(a[0]), "r"(a[1]), "r"(a[2]), "r"(a[3]), "r"(b[0]), "r"(b[1]));
}
#define CP16(dst, src) \
    asm volatile("cp.async.cg.shared.global [%0], [%1], 16;" :: "r"(dst), "l"(src))
#define CP_COMMIT() asm volatile("cp.async.commit_group;")
#define CP_WAIT1()  asm volatile("cp.async.wait_group 1;")

__device__ __forceinline__ uint32_t pack2(__half a, __half b) {
    return (uint32_t)__half_as_ushort(a) | ((uint32_t)__half_as_ushort(b) << 16);
}
__device__ __forceinline__ void split1(float x, __half& h, __half& l) {
    h = __float2half_rn(x);
    l = __float2half_rn(x - __half2float(h));
}
__device__ __forceinline__ float4 load4_split(const __half* hp, const __half* lp,
                                              long long idx) {
    uint2 h = *(const uint2*)(hp + idx);
    uint2 l = *(const uint2*)(lp + idx);
    const __half2 h0 = *reinterpret_cast<__half2*>(&h.x);
    const __half2 h1 = *reinterpret_cast<__half2*>(&h.y);
    const __half2 l0 = *reinterpret_cast<__half2*>(&l.x);
    const __half2 l1 = *reinterpret_cast<__half2*>(&l.y);
    float4 r;
    r.x = __half2float(h0.x) + __half2float(l0.x);
    r.y = __half2float(h0.y) + __half2float(l0.y);
    r.z = __half2float(h1.x) + __half2float(l1.x);
    r.w = __half2float(h1.y) + __half2float(l1.y);
    return r;
}

// ---------------- conversion kernels ---------------------------------------
__global__ __launch_bounds__(256)
void conv_pair(const float* __restrict__ src, __half* __restrict__ hi,
               __half* __restrict__ lo, int n4)
{
    const int i = blockIdx.x * 256 + threadIdx.x;
    if (i >= n4) return;
    float4 v = ((const float4*)src)[i];
    __half h0, h1, h2, h3, l0, l1, l2, l3;
    split1(v.x, h0, l0); split1(v.y, h1, l1);
    split1(v.z, h2, l2); split1(v.w, h3, l3);
    ((uint2*)hi)[i] = make_uint2(pack2(h0, h1), pack2(h2, h3));
    ((uint2*)lo)[i] = make_uint2(pack2(l0, l1), pack2(l2, l3));
}
__global__ __launch_bounds__(256)
void conv_hi(const float* __restrict__ src, __half* __restrict__ hi, int n4)
{
    const int i = blockIdx.x * 256 + threadIdx.x;
    if (i >= n4) return;
    float4 v = ((const float4*)src)[i];
    ((uint2*)hi)[i] = make_uint2(pack2(__float2half_rn(v.x), __float2half_rn(v.y)),
                                 pack2(__float2half_rn(v.z), __float2half_rn(v.w)));
}

// ---------------- GEMM geometry -------------------------------------------
// CTA 128x128, BK=32, 256 threads = 8 warps (2x4), warp tile 64x32.
// smem per stage: A hi+lo planes (128 x 80B) = 20480 B; B hi plane
// (32 x 272B) = 8704 B; stage = 29184 B, 3 stages = 87552 B.
// 2 CTAs/SM: 175KB smem (<228KB), 128 regs/thread cap (= full RF at 512 thr).
#define SA_ROWB  80
#define SA_PLANE 10240
#define SB_ROWB  272
#define SB_PLANE 8704
#define ST_A     20480
#define STAGE_B  29184
#define NSTAGE   3
#define SMEM_BYTES (STAGE_B * NSTAGE)

template<int KTOT, bool SPLIT_OUT>
__device__ __forceinline__
void gemm_body(const __half* __restrict__ Ahi, const __half* __restrict__ Alo,
               const __half* __restrict__ Bhi,
               float* __restrict__ Cf,
               __half* __restrict__ Chi, __half* __restrict__ Clo)
{
    extern __shared__ char sm[];
    const uint32_t smem_u = smem_u32(sm);

    const int tid  = threadIdx.x;
    const int wid  = tid >> 5;
    const int lane = tid & 31;
    const int bn   = blockIdx.x * 128;
    const int wm = (wid >> 2) * 64;
    const int wn = (wid & 3) * 32;
    const int sub = lane >> 3;
    const int lr  = lane & 7;

    const int ca0 = tid << 1;
    const int arow0 = ca0 >> 2,       aco0 = ca0 & 3;
    const int arow1 = (ca0 + 1) >> 2, aco1 = (ca0 + 1) & 3;
    const int brow0 = ca0 >> 4,       bco0 = ca0 & 15;
    const int brow1 = (ca0 + 1) >> 4, bco1 = (ca0 + 1) & 15;

    #define ISSUE(s, kt) do { \
        const uint32_t sb = smem_u + (s) * STAGE_B; \
        const __half* ga; uint32_t d; \
        ga = Ahi + arow0 * KTOT + (kt) * 32 + aco0 * 8; \
        d = sb + arow0 * SA_ROWB + aco0 * 16; \
        CP16(d, ga); CP16(d + SA_PLANE, ga + (Alo - Ahi)); \
        ga = Ahi + arow1 * KTOT + (kt) * 32 + aco1 * 8; \
        d = sb + arow1 * SA_ROWB + aco1 * 16; \
        CP16(d, ga); CP16(d + SA_PLANE, ga + (Alo - Ahi)); \
        ga = Bhi + (long long)((kt) * 32 + brow0) * HW + bn + bco0 * 8; \
        d = sb + ST_A + brow0 * SB_ROWB + bco0 * 16; \
        CP16(d, ga); \
        ga = Bhi + (long long)((kt) * 32 + brow1) * HW + bn + bco1 * 8; \
        d = sb + ST_A + brow1 * SB_ROWB + bco1 * 16; \
        CP16(d, ga); \
    } while (0)

    float acc[4][4][4];
    #pragma unroll
    for (int i = 0; i < 4; ++i)
        #pragma unroll
        for (int j = 0; j < 4; ++j)
            #pragma unroll
            for (int r = 0; r < 4; ++r) acc[i][j][r] = 0.f;

    constexpr int NK = KTOT / 32;
    ISSUE(0, 0); CP_COMMIT();
    ISSUE(1, 1); CP_COMMIT();

    int s = 0;
    #pragma unroll 1
    for (int t = 0; t < NK; ++t) {
        CP_WAIT1();
        __syncthreads();

        if (t + 2 < NK) {
            int s2 = s + 2; if (s2 >= NSTAGE) s2 -= NSTAGE;
            ISSUE(s2, t + 2);
        }
        CP_COMMIT();

        const uint32_t aB = smem_u + s * STAGE_B;
        const uint32_t bB = aB + ST_A;
        #pragma unroll
        for (int ks = 0; ks < 2; ++ks) {
            const int k0 = ks * 16;
            uint32_t ah[4][4], al[4][4], bh[2][4];
            #pragma unroll
            for (int i = 0; i < 4; ++i) {
                const int row = wm + 16 * i + (sub & 1) * 8 + lr;
                const int col = k0 + (sub >> 1) * 8;
                const uint32_t ab = aB + (uint32_t)row * SA_ROWB + (uint32_t)col * 2;
                ldsm_x4(ah[i][0], ah[i][1], ah[i][2], ah[i][3], ab);
                ldsm_x4(al[i][0], al[i][1], al[i][2], al[i][3], ab + SA_PLANE);
            }
            #pragma unroll
            for (int jj = 0; jj < 2; ++jj) {
                const int krow = k0 + (sub & 1) * 8 + lr;
                const int ncol = wn + 16 * jj + (sub >> 1) * 8;
                const uint32_t bb = bB + (uint32_t)krow * SB_ROWB + (uint32_t)ncol * 2;
                ldsm_x4_t(bh[jj][0], bh[jj][1], bh[jj][2], bh[jj][3], bb);
            }
            #pragma unroll
            for (int i = 0; i < 4; ++i)
                #pragma unroll
                for (int j = 0; j < 4; ++j) {
                    const uint32_t* bfh = &bh[j >> 1][(j & 1) * 2];
                    mma16816(acc[i][j], ah[i], bfh);   // hi*hi
                    mma16816(acc[i][j], al[i], bfh);   // lo*hi
                }
        }
        if (++s >= NSTAGE) s -= NSTAGE;
    }

    // epilogue
    const int g  = lane >> 2;
    const int tq = lane & 3;
    #pragma unroll
    for (int i = 0; i < 4; ++i)
        #pragma unroll
        for (int half = 0; half < 2; ++half) {
            const int row = wm + 16 * i + g + 8 * half;
            const long long rb = (long long)row * HW + bn + wn + 2 * tq;
            #pragma unroll
            for (int j = 0; j < 4; ++j) {
                const float v0 = acc[i][j][2 * half];
                const float v1 = acc[i][j][2 * half + 1];
                if constexpr (SPLIT_OUT) {
                    __half h0, h1, l0, l1;
                    split1(v0, h0, l0); split1(v1, h1, l1);
                    *(uint32_t*)(Chi + rb + 8 * j) = pack2(h0, h1);
                    *(uint32_t*)(Clo + rb + 8 * j) = pack2(l0, l1);
                } else {
                    *(float2*)(Cf + rb + 8 * j) = make_float2(v0, v1);
                }
            }
        }
    #undef ISSUE
}

__global__ __launch_bounds__(256, 2)
void k1_kernel()
{
    const long long z = blockIdx.z;
    const long long my = blockIdx.y;
    gemm_body<384, true>(g_wkvh + my * 128 * 384, g_wkvl + my * 128 * 384,
                         g_xh + z * C * HW,
                         nullptr,
                         g_kvh + z * 768 * HW + my * 128 * HW,
                         g_kvl + z * 768 * HW + my * 128 * HW);
}
__global__ __launch_bounds__(256, 2)
void k2_kernel()
{
    const long long z = blockIdx.z;
    const long long my = blockIdx.y;
    gemm_body<192, true>(g_wqh + my * 128 * 192, g_wql + my * 128 * 192,
                         g_yh + z * QC * HW,
                         nullptr,
                         g_qh + z * C * HW + my * 128 * HW,
                         g_ql + z * C * HW + my * 128 * HW);
}
__global__ __launch_bounds__(256, 2)
void k5_kernel(float* __restrict__ out)
{
    const long long z = blockIdx.z;
    const long long my = blockIdx.y;
    gemm_body<384, false>(g_weffh + z * C * C + my * 128 * C,
                          g_weffl + z * C * C + my * 128 * C,
                          g_kvh + z * 768 * HW + (long long)C * HW,
                          out + z * C * HW + my * 128 * HW,
                          nullptr, nullptr);
}

// ---------------- K3: Gram partials (4-way split over n) -------------------
__global__ __launch_bounds__(256)
void gram_kernel()
{
    const int bh = blockIdx.x;          // 0..127
    const int nq = blockIdx.y;          // 0..3
    const int b = bh >> 3, h = bh & 7;
    const long long qbase = ((long long)b * C   + h * DC) * HW;
    const long long kbase = ((long long)b * 768 + h * DC) * HW;

    __shared__ float qs[DC][65];
    __shared__ float ks[DC][65];

    const int tid = threadIdx.x;
    const int tx = tid & 15, ty = tid >> 4;

    float acc[3][3] = {};
    float nrm = 0.f;

    const int nbeg = nq * (HW / 4), nend = nbeg + (HW / 4);
    for (int n0 = nbeg; n0 < nend; n0 += 64) {
        for (int idx = tid; idx < DC * 16; idx += 256) {
            const int c = idx >> 4, nn4 = (idx & 15) << 2;
            float4 v = load4_split(g_qh, g_ql, qbase + (long long)c * HW + n0 + nn4);
            qs[c][nn4 + 0] = v.x; qs[c][nn4 + 1] = v.y; qs[c][nn4 + 2] = v.z; qs[c][nn4 + 3] = v.w;
            float4 w = load4_split(g_kvh, g_kvl, kbase + (long long)c * HW + n0 + nn4);
            ks[c][nn4 + 0] = w.x; ks[c][nn4 + 1] = w.y; ks[c][nn4 + 2] = w.z; ks[c][nn4 + 3] = w.w;
        }
        __syncthreads();
        #pragma unroll 4
        for (int nn = 0; nn < 64; ++nn) {
            const float a0 = qs[ty * 3 + 0][nn];
            const float a1 = qs[ty * 3 + 1][nn];
            const float a2 = qs[ty * 3 + 2][nn];
            const float b0 = ks[tx * 3 + 0][nn];
            const float b1 = ks[tx * 3 + 1][nn];
            const float b2 = ks[tx * 3 + 2][nn];
            acc[0][0] += a0 * b0; acc[0][1] += a0 * b1; acc[0][2] += a0 * b2;
            acc[1][0] += a1 * b0; acc[1][1] += a1 * b1; acc[1][2] += a1 * b2;
            acc[2][0] += a2 * b0; acc[2][1] += a2 * b1; acc[2][2] += a2 * b2;
        }
        if (tid < 96) {
            const float* row = (tid < DC) ? &qs[tid][0] : &ks[tid - DC][0];
            #pragma unroll 8
            for (int nn = 0; nn < 64; ++nn) { const float v = row[nn]; nrm += v * v; }
        }
        __syncthreads();
    }

    float* Sb = g_Sp + ((long long)nq * (B * HD) + bh) * DC * DC;
    #pragma unroll
    for (int i = 0; i < 3; i++)
        #pragma unroll
        for (int j = 0; j < 3; j++)
            Sb[(ty * 3 + i) * DC + (tx * 3 + j)] = acc[i][j];

    if (tid < DC)          g_qssp[nq * B * C + b * C + h * DC + tid]      = nrm;
    else if (tid < 2 * DC) g_kssp[nq * B * C + b * C + h * DC + tid - DC] = nrm;
}

// ---------------- K4a: softmax with folded L2 norms ------------------------
__global__ __launch_bounds__(64)
void k4a_softmax(const float* __restrict__ temp)
{
    const int bh = blockIdx.x;
    const int b = bh >> 3, h = bh & 7;
    const int tid = threadIdx.x;
    __shared__ float kinv[DC];

    if (tid < DC) {
        float kss = 0.f;
        #pragma unroll
        for (int p = 0; p < 4; ++p) kss += g_kssp[p * B * C + b * C + h * DC + tid];
        kinv[tid] = 1.f / fmaxf(sqrtf(kss), 1e-12f);
    }
    __syncthreads();

    if (tid < DC) {
        const int c = tid;
        float qss = 0.f;
        #pragma unroll
        for (int p = 0; p < 4; ++p) qss += g_qssp[p * B * C + b * C + h * DC + c];
        const float qinv = 1.f / fmaxf(sqrtf(qss), 1e-12f);
        const float T = temp[h];
        float vals[DC];
        float m = -INFINITY;
        #pragma unroll
        for (int d = 0; d < DC; d++) {
            float sv = 0.f;
            #pragma unroll
            for (int p = 0; p < 4; ++p)
                sv += g_Sp[((long long)p * (B * HD) + bh) * DC * DC + c * DC + d];
            const float l = sv * qinv * kinv[d] * T;
            vals[d] = l;
            m = fmaxf(m, l);
        }
        float ssum = 0.f;
        #pragma unroll
        for (int d = 0; d < DC; d++) { const float e = expf(vals[d] - m); vals[d] = e; ssum += e; }
        const float inv = 1.f / ssum;
        float* dst = g_attn + (long long)bh * DC * DC + c * DC;
        #pragma unroll
        for (int d = 0; d < DC; d++) dst[d] = vals[d] * inv;
    }
}

// ---------------- K4b: W_eff (split fp16 out) ------------------------------
__global__ __launch_bounds__(256)
void k4b_weff(const float* __restrict__ w_proj)
{
    const int og = blockIdx.x;   // 0..3, 96 output rows each
    const int b  = blockIdx.y;   // 0..15
    const int tid = threadIdx.x;
    __shared__ float attn_s[DC][DC + 1];
    __shared__ float w_s[96][DC];

    for (int h = 0; h < HD; ++h) {
        const float* a_src = g_attn + ((long long)(b * HD + h)) * DC * DC;
        for (int idx = tid; idx < DC * DC; idx += 256)
            attn_s[idx / DC][idx % DC] = a_src[idx];
        for (int idx = tid; idx < 96 * DC; idx += 256) {
            const int o = idx / DC, c = idx % DC;
            w_s[o][c] = w_proj[(long long)(og * 96 + o) * C + h * DC + c];
        }
        __syncthreads();
        for (int idx = tid; idx < 96 * DC; idx += 256) {
            const int o = idx / DC, d = idx % DC;
            float s = 0.f;
            #pragma unroll
            for (int c = 0; c < DC; ++c) s += w_s[o][c] * attn_s[c][d];
            const long long di = (long long)b * C * C + (long long)(og * 96 + o) * C + h * DC + d;
            __half hi, lo;
            split1(s, hi, lo);
            g_weffh[di] = hi;
            g_weffl[di] = lo;
        }
        __syncthreads();
    }
}

// ---------------- launch ---------------------------------------------------
extern "C" void kernel_launch(void* const* d_in, const int* in_sizes, int n_in,
                              void* d_out, int out_size)
{
    const float* x      = (const float*)d_in[0];
    const float* query  = (const float*)d_in[1];
    const float* w_kv   = (const float*)d_in[2];
    const float* w_q    = (const float*)d_in[3];
    const float* w_proj = (const float*)d_in[4];
    const float* temp   = (const float*)d_in[5];
    float* out = (float*)d_out;

    cudaFuncSetAttribute(k1_kernel, cudaFuncAttributeMaxDynamicSharedMemorySize, SMEM_BYTES);
    cudaFuncSetAttribute(k2_kernel, cudaFuncAttributeMaxDynamicSharedMemorySize, SMEM_BYTES);
    cudaFuncSetAttribute(k5_kernel, cudaFuncAttributeMaxDynamicSharedMemorySize, SMEM_BYTES);

    {
        __half *xh, *yh, *wkvh, *wkvl, *wqh, *wql;
        cudaGetSymbolAddress((void**)&xh, g_xh);
        cudaGetSymbolAddress((void**)&yh, g_yh);
        cudaGetSymbolAddress((void**)&wkvh, g_wkvh); cudaGetSymbolAddress((void**)&wkvl, g_wkvl);
        cudaGetSymbolAddress((void**)&wqh, g_wqh);   cudaGetSymbolAddress((void**)&wql, g_wql);
        conv_hi<<<(6291456 + 255) / 256, 256>>>(x, xh, 6291456);
        conv_hi<<<(3145728 + 255) / 256, 256>>>(query, yh, 3145728);
        conv_pair<<<(73728 + 255) / 256, 256>>>(w_kv, wkvh, wkvl, 73728);
        conv_pair<<<(18432 + 255) / 256, 256>>>(w_q, wqh, wql, 18432);
    }

    k1_kernel<<<dim3(HW / 128, 6, B), 256, SMEM_BYTES>>>();
    k2_kernel<<<dim3(HW / 128, 3, B), 256, SMEM_BYTES>>>();
    gram_kernel<<<dim3(B * HD, 4), 256>>>();
    k4a_softmax<<<B * HD, 64>>>(temp);
    k4b_weff<<<dim3(4, B), 256>>>(w_proj);
    k5_kernel<<<dim3(HW / 128, 3, B), 256, SMEM_BYTES>>>(out);
}

// round 10
// speedup vs baseline: 2.7948x; 1.1802x over previous
#include <cuda_runtime.h>
#include <cuda_fp16.h>
#include <math.h>
#include <cstdint>

// ============================================================================
// CrossAttention — mma.sync fp16 2-term split, v eliminated by composition.
//
//  conv: w_k -> hi/lo; w_v -> hi; w_q -> hi/lo; x,query -> hi
//  K1: k  = w_k(hi+lo) @ x(hi)    -> k stored fp16 hi/lo      [mma.sync]
//  K2: q  = w_q(hi+lo) @ query(hi) -> q stored fp16 hi/lo     [mma.sync]
//  K3: Gram S = q.k^T (hi+lo reconstruct), 4-way split-n      [SIMT]
//  K4a: softmax (L2-norm folded)                              [SIMT]
//  K4b: W_eff = w_proj_blockdiag @ attn -> fp16 hi/lo         [SIMT]
//  KW2: W2 = W_eff(hi+lo) @ w_v(hi)  -> fp16 hi/lo            [mma.sync]
//  K5: out = W2(hi+lo) @ x(hi) -> fp32                        [mma.sync]
//
// out = W_eff·(w_v·x) = (W_eff·w_v)·x : v (19.3G math + 200MB traffic)
// never computed. Total MMA-FLOP 135G -> 100G.
// ============================================================================

#define B   16
#define C   384
#define QC  192
#define HD  8
#define DC  48
#define HW  4096

// ---------------- scratch (fp16 planes) ------------------------------------
__device__ __half g_xh [(long long)B * C * HW];
__device__ __half g_yh [(long long)B * QC * HW];
__device__ __half g_kh [(long long)B * C * HW];
__device__ __half g_kl [(long long)B * C * HW];
__device__ __half g_qh [(long long)B * C * HW];
__device__ __half g_ql [(long long)B * C * HW];
__device__ __half g_wkh[384 * 384], g_wkl[384 * 384];
__device__ __half g_wvh[384 * 384];
__device__ __half g_wqh[384 * 192], g_wql[384 * 192];
__device__ __half g_weffh[(long long)B * C * C], g_weffl[(long long)B * C * C];
__device__ __half g_w2h[(long long)B * C * C], g_w2l[(long long)B * C * C];
__device__ float g_Sp  [4 * B * HD * DC * DC];
__device__ float g_qssp[4 * B * C];
__device__ float g_kssp[4 * B * C];
__device__ float g_attn[(long long)B * HD * DC * DC];

// ---------------- helpers --------------------------------------------------
__device__ __forceinline__ uint32_t smem_u32(const void* p) {
    uint32_t a;
    asm("{ .reg .u64 t; cvta.to.shared.u64 t, %1; cvt.u32.u64 %0, t; }" : "=r"(a) : "l"(p));
    return a;
}
__device__ __forceinline__ void ldsm_x4(uint32_t& r0, uint32_t& r1, uint32_t& r2, uint32_t& r3,
                                        uint32_t addr) {
    asm volatile("ldmatrix.sync.aligned.m8n8.x4.shared.b16 {%0,%1,%2,%3}, [%4];"
                 : "=r"(r0), "=r"(r1), "=r"(r2), "=r"(r3) : "r"(addr));
}
__device__ __forceinline__ void ldsm_x4_t(uint32_t& r0, uint32_t& r1, uint32_t& r2, uint32_t& r3,
                                          uint32_t addr) {
    asm volatile("ldmatrix.sync.aligned.m8n8.x4.trans.shared.b16 {%0,%1,%2,%3}, [%4];"
                 : "=r"(r0), "=r"(r1), "=r"(r2), "=r"(r3) : "r"(addr));
}
__device__ __forceinline__ void mma16816(float* c, const uint32_t* a, const uint32_t* b) {
    asm volatile("mma.sync.aligned.m16n8k16.row.col.f32.f16.f16.f32 "
                 "{%0,%1,%2,%3}, {%4,%5,%6,%7}, {%8,%9}, {%0,%1,%2,%3};"
                 : "+f"(c[0]), "+f"(c[1]), "+f"(c[2]), "+f"(c[3])
                 : "r"(a[0]), "r"(a[1]), "r"(a[2]), "r"(a[3]), "r"(b[0]), "r"(b[1]));
}
#define CP16(dst, src) \
    asm volatile("cp.async.cg.shared.global [%0], [%1], 16;" :: "r"(dst), "l"(src))
#define CP_COMMIT() asm volatile("cp.async.commit_group;")
#define CP_WAIT1()  asm volatile("cp.async.wait_group 1;")

__device__ __forceinline__ uint32_t pack2(__half a, __half b) {
    return (uint32_t)__half_as_ushort(a) | ((uint32_t)__half_as_ushort(b) << 16);
}
__device__ __forceinline__ void split1(float x, __half& h, __half& l) {
    h = __float2half_rn(x);
    l = __float2half_rn(x - __half2float(h));
}
__device__ __forceinline__ float4 load4_split(const __half* hp, const __half* lp,
                                              long long idx) {
    uint2 h = *(const uint2*)(hp + idx);
    uint2 l = *(const uint2*)(lp + idx);
    const __half2 h0 = *reinterpret_cast<__half2*>(&h.x);
    const __half2 h1 = *reinterpret_cast<__half2*>(&h.y);
    const __half2 l0 = *reinterpret_cast<__half2*>(&l.x);
    const __half2 l1 = *reinterpret_cast<__half2*>(&l.y);
    float4 r;
    r.x = __half2float(h0.x) + __half2float(l0.x);
    r.y = __half2float(h0.y) + __half2float(l0.y);
    r.z = __half2float(h1.x) + __half2float(l1.x);
    r.w = __half2float(h1.y) + __half2float(l1.y);
    return r;
}

// ---------------- conversion kernels ---------------------------------------
__global__ __launch_bounds__(256)
void conv_pair(const float* __restrict__ src, __half* __restrict__ hi,
               __half* __restrict__ lo, int n4)
{
    const int i = blockIdx.x * 256 + threadIdx.x;
    if (i >= n4) return;
    float4 v = ((const float4*)src)[i];
    __half h0, h1, h2, h3, l0, l1, l2, l3;
    split1(v.x, h0, l0); split1(v.y, h1, l1);
    split1(v.z, h2, l2); split1(v.w, h3, l3);
    ((uint2*)hi)[i] = make_uint2(pack2(h0, h1), pack2(h2, h3));
    ((uint2*)lo)[i] = make_uint2(pack2(l0, l1), pack2(l2, l3));
}
__global__ __launch_bounds__(256)
void conv_hi(const float* __restrict__ src, __half* __restrict__ hi, int n4)
{
    const int i = blockIdx.x * 256 + threadIdx.x;
    if (i >= n4) return;
    float4 v = ((const float4*)src)[i];
    ((uint2*)hi)[i] = make_uint2(pack2(__float2half_rn(v.x), __float2half_rn(v.y)),
                                 pack2(__float2half_rn(v.z), __float2half_rn(v.w)));
}

// ---------------- GEMM geometry -------------------------------------------
// CTA 128x128, BK=32, 256 threads = 8 warps (2x4), warp tile 64x32.
// smem per stage: A hi+lo planes (128 x 80B) = 20480 B; B hi plane
// (32 x 272B) = 8704 B; stage = 29184 B, 3 stages = 87552 B. 2 CTAs/SM.
#define SA_ROWB  80
#define SA_PLANE 10240
#define SB_ROWB  272
#define SB_PLANE 8704
#define ST_A     20480
#define STAGE_B  29184
#define NSTAGE   3
#define SMEM_BYTES (STAGE_B * NSTAGE)

template<int KTOT, int LDB, int LDC, bool SPLIT_OUT>
__device__ __forceinline__
void gemm_body(const __half* __restrict__ Ahi, const __half* __restrict__ Alo,
               const __half* __restrict__ Bhi,
               float* __restrict__ Cf,
               __half* __restrict__ Chi, __half* __restrict__ Clo)
{
    extern __shared__ char sm[];
    const uint32_t smem_u = smem_u32(sm);

    const int tid  = threadIdx.x;
    const int wid  = tid >> 5;
    const int lane = tid & 31;
    const int bn   = blockIdx.x * 128;
    const int wm = (wid >> 2) * 64;
    const int wn = (wid & 3) * 32;
    const int sub = lane >> 3;
    const int lr  = lane & 7;

    const int ca0 = tid << 1;
    const int arow0 = ca0 >> 2,       aco0 = ca0 & 3;
    const int arow1 = (ca0 + 1) >> 2, aco1 = (ca0 + 1) & 3;
    const int brow0 = ca0 >> 4,       bco0 = ca0 & 15;
    const int brow1 = (ca0 + 1) >> 4, bco1 = (ca0 + 1) & 15;

    #define ISSUE(s, kt) do { \
        const uint32_t sb = smem_u + (s) * STAGE_B; \
        const __half* ga; uint32_t d; \
        ga = Ahi + arow0 * KTOT + (kt) * 32 + aco0 * 8; \
        d = sb + arow0 * SA_ROWB + aco0 * 16; \
        CP16(d, ga); CP16(d + SA_PLANE, ga + (Alo - Ahi)); \
        ga = Ahi + arow1 * KTOT + (kt) * 32 + aco1 * 8; \
        d = sb + arow1 * SA_ROWB + aco1 * 16; \
        CP16(d, ga); CP16(d + SA_PLANE, ga + (Alo - Ahi)); \
        ga = Bhi + (long long)((kt) * 32 + brow0) * LDB + bn + bco0 * 8; \
        d = sb + ST_A + brow0 * SB_ROWB + bco0 * 16; \
        CP16(d, ga); \
        ga = Bhi + (long long)((kt) * 32 + brow1) * LDB + bn + bco1 * 8; \
        d = sb + ST_A + brow1 * SB_ROWB + bco1 * 16; \
        CP16(d, ga); \
    } while (0)

    float acc[4][4][4];
    #pragma unroll
    for (int i = 0; i < 4; ++i)
        #pragma unroll
        for (int j = 0; j < 4; ++j)
            #pragma unroll
            for (int r = 0; r < 4; ++r) acc[i][j][r] = 0.f;

    constexpr int NK = KTOT / 32;
    ISSUE(0, 0); CP_COMMIT();
    ISSUE(1, 1); CP_COMMIT();

    int s = 0;
    #pragma unroll 1
    for (int t = 0; t < NK; ++t) {
        CP_WAIT1();
        __syncthreads();

        if (t + 2 < NK) {
            int s2 = s + 2; if (s2 >= NSTAGE) s2 -= NSTAGE;
            ISSUE(s2, t + 2);
        }
        CP_COMMIT();

        const uint32_t aB = smem_u + s * STAGE_B;
        const uint32_t bB = aB + ST_A;
        #pragma unroll
        for (int ks = 0; ks < 2; ++ks) {
            const int k0 = ks * 16;
            uint32_t ah[4][4], al[4][4], bh[2][4];
            #pragma unroll
            for (int i = 0; i < 4; ++i) {
                const int row = wm + 16 * i + (sub & 1) * 8 + lr;
                const int col = k0 + (sub >> 1) * 8;
                const uint32_t ab = aB + (uint32_t)row * SA_ROWB + (uint32_t)col * 2;
                ldsm_x4(ah[i][0], ah[i][1], ah[i][2], ah[i][3], ab);
                ldsm_x4(al[i][0], al[i][1], al[i][2], al[i][3], ab + SA_PLANE);
            }
            #pragma unroll
            for (int jj = 0; jj < 2; ++jj) {
                const int krow = k0 + (sub & 1) * 8 + lr;
                const int ncol = wn + 16 * jj + (sub >> 1) * 8;
                const uint32_t bb = bB + (uint32_t)krow * SB_ROWB + (uint32_t)ncol * 2;
                ldsm_x4_t(bh[jj][0], bh[jj][1], bh[jj][2], bh[jj][3], bb);
            }
            #pragma unroll
            for (int i = 0; i < 4; ++i)
                #pragma unroll
                for (int j = 0; j < 4; ++j) {
                    const uint32_t* bfh = &bh[j >> 1][(j & 1) * 2];
                    mma16816(acc[i][j], ah[i], bfh);   // hi*hi
                    mma16816(acc[i][j], al[i], bfh);   // lo*hi
                }
        }
        if (++s >= NSTAGE) s -= NSTAGE;
    }

    // epilogue
    const int g  = lane >> 2;
    const int tq = lane & 3;
    #pragma unroll
    for (int i = 0; i < 4; ++i)
        #pragma unroll
        for (int half = 0; half < 2; ++half) {
            const int row = wm + 16 * i + g + 8 * half;
            const long long rb = (long long)row * LDC + bn + wn + 2 * tq;
            #pragma unroll
            for (int j = 0; j < 4; ++j) {
                const float v0 = acc[i][j][2 * half];
                const float v1 = acc[i][j][2 * half + 1];
                if constexpr (SPLIT_OUT) {
                    __half h0, h1, l0, l1;
                    split1(v0, h0, l0); split1(v1, h1, l1);
                    *(uint32_t*)(Chi + rb + 8 * j) = pack2(h0, h1);
                    *(uint32_t*)(Clo + rb + 8 * j) = pack2(l0, l1);
                } else {
                    *(float2*)(Cf + rb + 8 * j) = make_float2(v0, v1);
                }
            }
        }
    #undef ISSUE
}

__global__ __launch_bounds__(256, 2)
void k1_kernel()   // k = w_k @ x
{
    const long long z = blockIdx.z;
    const long long my = blockIdx.y;
    gemm_body<384, HW, HW, true>(g_wkh + my * 128 * 384, g_wkl + my * 128 * 384,
                                 g_xh + z * C * HW,
                                 nullptr,
                                 g_kh + z * C * HW + my * 128 * HW,
                                 g_kl + z * C * HW + my * 128 * HW);
}
__global__ __launch_bounds__(256, 2)
void k2_kernel()   // q = w_q @ query
{
    const long long z = blockIdx.z;
    const long long my = blockIdx.y;
    gemm_body<192, HW, HW, true>(g_wqh + my * 128 * 192, g_wql + my * 128 * 192,
                                 g_yh + z * QC * HW,
                                 nullptr,
                                 g_qh + z * C * HW + my * 128 * HW,
                                 g_ql + z * C * HW + my * 128 * HW);
}
__global__ __launch_bounds__(256, 2)
void kw2_kernel()  // W2 = W_eff @ w_v   (per batch, N=384)
{
    const long long z = blockIdx.z;
    const long long my = blockIdx.y;
    gemm_body<384, 384, 384, true>(g_weffh + z * C * C + my * 128 * C,
                                   g_weffl + z * C * C + my * 128 * C,
                                   g_wvh,
                                   nullptr,
                                   g_w2h + z * C * C + my * 128 * C,
                                   g_w2l + z * C * C + my * 128 * C);
}
__global__ __launch_bounds__(256, 2)
void k5_kernel(float* __restrict__ out)   // out = W2 @ x
{
    const long long z = blockIdx.z;
    const long long my = blockIdx.y;
    gemm_body<384, HW, HW, false>(g_w2h + z * C * C + my * 128 * C,
                                  g_w2l + z * C * C + my * 128 * C,
                                  g_xh + z * C * HW,
                                  out + z * C * HW + my * 128 * HW,
                                  nullptr, nullptr);
}

// ---------------- K3: Gram partials (4-way split over n) -------------------
__global__ __launch_bounds__(256)
void gram_kernel()
{
    const int bh = blockIdx.x;          // 0..127
    const int nq = blockIdx.y;          // 0..3
    const int b = bh >> 3, h = bh & 7;
    const long long qbase = ((long long)b * C + h * DC) * HW;
    const long long kbase = ((long long)b * C + h * DC) * HW;

    __shared__ float qs[DC][65];
    __shared__ float ks[DC][65];

    const int tid = threadIdx.x;
    const int tx = tid & 15, ty = tid >> 4;

    float acc[3][3] = {};
    float nrm = 0.f;

    const int nbeg = nq * (HW / 4), nend = nbeg + (HW / 4);
    for (int n0 = nbeg; n0 < nend; n0 += 64) {
        for (int idx = tid; idx < DC * 16; idx += 256) {
            const int c = idx >> 4, nn4 = (idx & 15) << 2;
            float4 v = load4_split(g_qh, g_ql, qbase + (long long)c * HW + n0 + nn4);
            qs[c][nn4 + 0] = v.x; qs[c][nn4 + 1] = v.y; qs[c][nn4 + 2] = v.z; qs[c][nn4 + 3] = v.w;
            float4 w = load4_split(g_kh, g_kl, kbase + (long long)c * HW + n0 + nn4);
            ks[c][nn4 + 0] = w.x; ks[c][nn4 + 1] = w.y; ks[c][nn4 + 2] = w.z; ks[c][nn4 + 3] = w.w;
        }
        __syncthreads();
        #pragma unroll 4
        for (int nn = 0; nn < 64; ++nn) {
            const float a0 = qs[ty * 3 + 0][nn];
            const float a1 = qs[ty * 3 + 1][nn];
            const float a2 = qs[ty * 3 + 2][nn];
            const float b0 = ks[tx * 3 + 0][nn];
            const float b1 = ks[tx * 3 + 1][nn];
            const float b2 = ks[tx * 3 + 2][nn];
            acc[0][0] += a0 * b0; acc[0][1] += a0 * b1; acc[0][2] += a0 * b2;
            acc[1][0] += a1 * b0; acc[1][1] += a1 * b1; acc[1][2] += a1 * b2;
            acc[2][0] += a2 * b0; acc[2][1] += a2 * b1; acc[2][2] += a2 * b2;
        }
        if (tid < 96) {
            const float* row = (tid < DC) ? &qs[tid][0] : &ks[tid - DC][0];
            #pragma unroll 8
            for (int nn = 0; nn < 64; ++nn) { const float v = row[nn]; nrm += v * v; }
        }
        __syncthreads();
    }

    float* Sb = g_Sp + ((long long)nq * (B * HD) + bh) * DC * DC;
    #pragma unroll
    for (int i = 0; i < 3; i++)
        #pragma unroll
        for (int j = 0; j < 3; j++)
            Sb[(ty * 3 + i) * DC + (tx * 3 + j)] = acc[i][j];

    if (tid < DC)          g_qssp[nq * B * C + b * C + h * DC + tid]      = nrm;
    else if (tid < 2 * DC) g_kssp[nq * B * C + b * C + h * DC + tid - DC] = nrm;
}

// ---------------- K4a: softmax with folded L2 norms ------------------------
__global__ __launch_bounds__(64)
void k4a_softmax(const float* __restrict__ temp)
{
    const int bh = blockIdx.x;
    const int b = bh >> 3, h = bh & 7;
    const int tid = threadIdx.x;
    __shared__ float kinv[DC];

    if (tid < DC) {
        float kss = 0.f;
        #pragma unroll
        for (int p = 0; p < 4; ++p) kss += g_kssp[p * B * C + b * C + h * DC + tid];
        kinv[tid] = 1.f / fmaxf(sqrtf(kss), 1e-12f);
    }
    __syncthreads();

    if (tid < DC) {
        const int c = tid;
        float qss = 0.f;
        #pragma unroll
        for (int p = 0; p < 4; ++p) qss += g_qssp[p * B * C + b * C + h * DC + c];
        const float qinv = 1.f / fmaxf(sqrtf(qss), 1e-12f);
        const float T = temp[h];
        float vals[DC];
        float m = -INFINITY;
        #pragma unroll
        for (int d = 0; d < DC; d++) {
            float sv = 0.f;
            #pragma unroll
            for (int p = 0; p < 4; ++p)
                sv += g_Sp[((long long)p * (B * HD) + bh) * DC * DC + c * DC + d];
            const float l = sv * qinv * kinv[d] * T;
            vals[d] = l;
            m = fmaxf(m, l);
        }
        float ssum = 0.f;
        #pragma unroll
        for (int d = 0; d < DC; d++) { const float e = expf(vals[d] - m); vals[d] = e; ssum += e; }
        const float inv = 1.f / ssum;
        float* dst = g_attn + (long long)bh * DC * DC + c * DC;
        #pragma unroll
        for (int d = 0; d < DC; d++) dst[d] = vals[d] * inv;
    }
}

// ---------------- K4b: W_eff (split fp16 out) ------------------------------
__global__ __launch_bounds__(256)
void k4b_weff(const float* __restrict__ w_proj)
{
    const int og = blockIdx.x;   // 0..3, 96 output rows each
    const int b  = blockIdx.y;   // 0..15
    const int tid = threadIdx.x;
    __shared__ float attn_s[DC][DC + 1];
    __shared__ float w_s[96][DC];

    for (int h = 0; h < HD; ++h) {
        const float* a_src = g_attn + ((long long)(b * HD + h)) * DC * DC;
        for (int idx = tid; idx < DC * DC; idx += 256)
            attn_s[idx / DC][idx % DC] = a_src[idx];
        for (int idx = tid; idx < 96 * DC; idx += 256) {
            const int o = idx / DC, c = idx % DC;
            w_s[o][c] = w_proj[(long long)(og * 96 + o) * C + h * DC + c];
        }
        __syncthreads();
        for (int idx = tid; idx < 96 * DC; idx += 256) {
            const int o = idx / DC, d = idx % DC;
            float s = 0.f;
            #pragma unroll
            for (int c = 0; c < DC; ++c) s += w_s[o][c] * attn_s[c][d];
            const long long di = (long long)b * C * C + (long long)(og * 96 + o) * C + h * DC + d;
            __half hi, lo;
            split1(s, hi, lo);
            g_weffh[di] = hi;
            g_weffl[di] = lo;
        }
        __syncthreads();
    }
}

// ---------------- launch ---------------------------------------------------
extern "C" void kernel_launch(void* const* d_in, const int* in_sizes, int n_in,
                              void* d_out, int out_size)
{
    const float* x      = (const float*)d_in[0];
    const float* query  = (const float*)d_in[1];
    const float* w_kv   = (const float*)d_in[2];
    const float* w_q    = (const float*)d_in[3];
    const float* w_proj = (const float*)d_in[4];
    const float* temp   = (const float*)d_in[5];
    float* out = (float*)d_out;

    cudaFuncSetAttribute(k1_kernel,  cudaFuncAttributeMaxDynamicSharedMemorySize, SMEM_BYTES);
    cudaFuncSetAttribute(k2_kernel,  cudaFuncAttributeMaxDynamicSharedMemorySize, SMEM_BYTES);
    cudaFuncSetAttribute(kw2_kernel, cudaFuncAttributeMaxDynamicSharedMemorySize, SMEM_BYTES);
    cudaFuncSetAttribute(k5_kernel,  cudaFuncAttributeMaxDynamicSharedMemorySize, SMEM_BYTES);

    {
        __half *xh, *yh, *wkh, *wkl, *wvh, *wqh, *wql;
        cudaGetSymbolAddress((void**)&xh, g_xh);
        cudaGetSymbolAddress((void**)&yh, g_yh);
        cudaGetSymbolAddress((void**)&wkh, g_wkh); cudaGetSymbolAddress((void**)&wkl, g_wkl);
        cudaGetSymbolAddress((void**)&wvh, g_wvh);
        cudaGetSymbolAddress((void**)&wqh, g_wqh); cudaGetSymbolAddress((void**)&wql, g_wql);
        conv_hi<<<(6291456 + 255) / 256, 256>>>(x, xh, 6291456);
        conv_hi<<<(3145728 + 255) / 256, 256>>>(query, yh, 3145728);
        conv_pair<<<(36864 + 255) / 256, 256>>>(w_kv, wkh, wkl, 36864);           // k rows
        conv_hi<<<(36864 + 255) / 256, 256>>>(w_kv + 384 * 384, wvh, 36864);      // v rows
        conv_pair<<<(18432 + 255) / 256, 256>>>(w_q, wqh, wql, 18432);
    }

    k1_kernel<<<dim3(HW / 128, 3, B), 256, SMEM_BYTES>>>();
    k2_kernel<<<dim3(HW / 128, 3, B), 256, SMEM_BYTES>>>();
    gram_kernel<<<dim3(B * HD, 4), 256>>>();
    k4a_softmax<<<B * HD, 64>>>(temp);
    k4b_weff<<<dim3(4, B), 256>>>(w_proj);
    kw2_kernel<<<dim3(3, 3, B), 256, SMEM_BYTES>>>();
    k5_kernel<<<dim3(HW / 128, 3, B), 256, SMEM_BYTES>>>(out);
}

// round 11
// speedup vs baseline: 3.2558x; 1.1649x over previous
#include <cuda_runtime.h>
#include <cuda_fp16.h>
#include <math.h>
#include <cstdint>

// ============================================================================
// CrossAttention — mma.sync fp16, v eliminated, single-plane k/q path.
//
//  conv_all: x,query -> fp16 hi; w_k -> hi/lo... actually w_k,w_q -> hi only
//            now? NO: w_k/w_q single-plane too (K1/K2 are 1-term).
//            w_v -> hi. w_k,w_q -> hi. (lo planes only for W_eff/W2 path)
//  K12: k = w_k(hi) @ x(hi); q = w_q(hi) @ query(hi)  [merged, mma.sync]
//       outputs stored fp16 hi/lo (of the computed fp32)
//  K3: Gram S = q.k^T (hi+lo reconstruct), 4-way split-n      [SIMT]
//  K4a: softmax (L2-norm folded)                              [SIMT]
//  K4b: W_eff = w_proj_blockdiag @ attn -> fp16 hi/lo         [SIMT]
//  KW2: W2 = W_eff(hi+lo) @ w_v(hi)  -> fp16 hi/lo  [2-term mma.sync]
//  K5: out = W2(hi+lo) @ x(hi) -> fp32              [2-term mma.sync]
//
// Error budget: k/q carry ~3.4e-4 (w + x fp16 roundings) but feed only the
// L2-normalized softmax path (scale errors cancel); direct path (W2@x)
// keeps 2-term split-A. Predicted total ~4e-4 vs 1e-3 gate.
// ============================================================================

#define B   16
#define C   384
#define QC  192
#define HD  8
#define DC  48
#define HW  4096

// ---------------- scratch (fp16 planes) ------------------------------------
__device__ __half g_xh [(long long)B * C * HW];
__device__ __half g_yh [(long long)B * QC * HW];
__device__ __half g_kh [(long long)B * C * HW];
__device__ __half g_kl [(long long)B * C * HW];
__device__ __half g_qh [(long long)B * C * HW];
__device__ __half g_ql [(long long)B * C * HW];
__device__ __half g_wkh[384 * 384];
__device__ __half g_wvh[384 * 384];
__device__ __half g_wqh[384 * 192];
__device__ __half g_weffh[(long long)B * C * C], g_weffl[(long long)B * C * C];
__device__ __half g_w2h[(long long)B * C * C], g_w2l[(long long)B * C * C];
__device__ float g_Sp  [4 * B * HD * DC * DC];
__device__ float g_qssp[4 * B * C];
__device__ float g_kssp[4 * B * C];
__device__ float g_attn[(long long)B * HD * DC * DC];

// ---------------- helpers --------------------------------------------------
__device__ __forceinline__ uint32_t smem_u32(const void* p) {
    uint32_t a;
    asm("{ .reg .u64 t; cvta.to.shared.u64 t, %1; cvt.u32.u64 %0, t; }" : "=r"(a) : "l"(p));
    return a;
}
__device__ __forceinline__ void ldsm_x4(uint32_t& r0, uint32_t& r1, uint32_t& r2, uint32_t& r3,
                                        uint32_t addr) {
    asm volatile("ldmatrix.sync.aligned.m8n8.x4.shared.b16 {%0,%1,%2,%3}, [%4];"
                 : "=r"(r0), "=r"(r1), "=r"(r2), "=r"(r3) : "r"(addr));
}
__device__ __forceinline__ void ldsm_x4_t(uint32_t& r0, uint32_t& r1, uint32_t& r2, uint32_t& r3,
                                          uint32_t addr) {
    asm volatile("ldmatrix.sync.aligned.m8n8.x4.trans.shared.b16 {%0,%1,%2,%3}, [%4];"
                 : "=r"(r0), "=r"(r1), "=r"(r2), "=r"(r3) : "r"(addr));
}
__device__ __forceinline__ void mma16816(float* c, const uint32_t* a, const uint32_t* b) {
    asm volatile("mma.sync.aligned.m16n8k16.row.col.f32.f16.f16.f32 "
                 "{%0,%1,%2,%3}, {%4,%5,%6,%7}, {%8,%9}, {%0,%1,%2,%3};"
                 : "+f"(c[0]), "+f"(c[1]), "+f"(c[2]), "+f"(c[3])
                 : "r"(a[0]), "r"(a[1]), "r"(a[2]), "r"(a[3]), "r"(b[0]), "r"(b[1]));
}
#define CP16(dst, src) \
    asm volatile("cp.async.cg.shared.global [%0], [%1], 16;" :: "r"(dst), "l"(src))
#define CP_COMMIT() asm volatile("cp.async.commit_group;")
#define CP_WAIT1()  asm volatile("cp.async.wait_group 1;")

__device__ __forceinline__ uint32_t pack2(__half a, __half b) {
    return (uint32_t)__half_as_ushort(a) | ((uint32_t)__half_as_ushort(b) << 16);
}
__device__ __forceinline__ void split1(float x, __half& h, __half& l) {
    h = __float2half_rn(x);
    l = __float2half_rn(x - __half2float(h));
}
__device__ __forceinline__ float4 load4_split(const __half* hp, const __half* lp,
                                              long long idx) {
    uint2 h = *(const uint2*)(hp + idx);
    uint2 l = *(const uint2*)(lp + idx);
    const __half2 h0 = *reinterpret_cast<__half2*>(&h.x);
    const __half2 h1 = *reinterpret_cast<__half2*>(&h.y);
    const __half2 l0 = *reinterpret_cast<__half2*>(&l.x);
    const __half2 l1 = *reinterpret_cast<__half2*>(&l.y);
    float4 r;
    r.x = __half2float(h0.x) + __half2float(l0.x);
    r.y = __half2float(h0.y) + __half2float(l0.y);
    r.z = __half2float(h1.x) + __half2float(l1.x);
    r.w = __half2float(h1.y) + __half2float(l1.y);
    return r;
}

// ---------------- merged conversion kernel ---------------------------------
// float4-unit segments:
//  [0, 6291456)                x      -> g_xh (hi)
//  [6291456, 9437184)          query  -> g_yh (hi)
//  [9437184, 9474048)          w_k    -> g_wkh (hi)
//  [9474048, 9510912)          w_v    -> g_wvh (hi)
//  [9510912, 9529344)          w_q    -> g_wqh (hi)
#define CONV_TOT 9529344
__global__ __launch_bounds__(256)
void conv_all(const float* __restrict__ x, const float* __restrict__ query,
              const float* __restrict__ w_kv, const float* __restrict__ w_q)
{
    const long long i = (long long)blockIdx.x * 256 + threadIdx.x;
    if (i >= CONV_TOT) return;
    const float4* src;
    __half* dst;
    long long j;
    if (i < 6291456) {
        j = i; src = (const float4*)x; dst = g_xh;
    } else if (i < 9437184) {
        j = i - 6291456; src = (const float4*)query; dst = g_yh;
    } else if (i < 9474048) {
        j = i - 9437184; src = (const float4*)w_kv; dst = g_wkh;
    } else if (i < 9510912) {
        j = i - 9474048; src = (const float4*)w_kv + 36864; dst = g_wvh;
    } else {
        j = i - 9510912; src = (const float4*)w_q; dst = g_wqh;
    }
    float4 v = src[j];
    ((uint2*)dst)[j] = make_uint2(pack2(__float2half_rn(v.x), __float2half_rn(v.y)),
                                  pack2(__float2half_rn(v.z), __float2half_rn(v.w)));
}

// ---------------- GEMM geometry -------------------------------------------
// CTA 128x128, BK=32, 256 threads = 8 warps (2x4), warp tile 64x32.
// smem per stage: A hi(+lo) planes (128 x 80B) = 10240(x2) B; B hi plane
// (32 x 272B) = 8704 B. Fixed stage layout (split-A size) for simplicity.
#define SA_ROWB  80
#define SA_PLANE 10240
#define SB_ROWB  272
#define SB_PLANE 8704
#define ST_A     20480
#define STAGE_B  29184
#define NSTAGE   3
#define SMEM_BYTES (STAGE_B * NSTAGE)

template<int KTOT, int LDB, int LDC, bool SPLIT_A, bool SPLIT_OUT>
__device__ __forceinline__
void gemm_body(const __half* __restrict__ Ahi, const __half* __restrict__ Alo,
               const __half* __restrict__ Bhi,
               float* __restrict__ Cf,
               __half* __restrict__ Chi, __half* __restrict__ Clo)
{
    extern __shared__ char sm[];
    const uint32_t smem_u = smem_u32(sm);

    const int tid  = threadIdx.x;
    const int wid  = tid >> 5;
    const int lane = tid & 31;
    const int bn   = blockIdx.x * 128;
    const int wm = (wid >> 2) * 64;
    const int wn = (wid & 3) * 32;
    const int sub = lane >> 3;
    const int lr  = lane & 7;

    const int ca0 = tid << 1;
    const int arow0 = ca0 >> 2,       aco0 = ca0 & 3;
    const int arow1 = (ca0 + 1) >> 2, aco1 = (ca0 + 1) & 3;
    const int brow0 = ca0 >> 4,       bco0 = ca0 & 15;
    const int brow1 = (ca0 + 1) >> 4, bco1 = (ca0 + 1) & 15;

    #define ISSUE(s, kt) do { \
        const uint32_t sb = smem_u + (s) * STAGE_B; \
        const __half* ga; uint32_t d; \
        ga = Ahi + arow0 * KTOT + (kt) * 32 + aco0 * 8; \
        d = sb + arow0 * SA_ROWB + aco0 * 16; \
        CP16(d, ga); \
        if constexpr (SPLIT_A) { CP16(d + SA_PLANE, ga + (Alo - Ahi)); } \
        ga = Ahi + arow1 * KTOT + (kt) * 32 + aco1 * 8; \
        d = sb + arow1 * SA_ROWB + aco1 * 16; \
        CP16(d, ga); \
        if constexpr (SPLIT_A) { CP16(d + SA_PLANE, ga + (Alo - Ahi)); } \
        ga = Bhi + (long long)((kt) * 32 + brow0) * LDB + bn + bco0 * 8; \
        d = sb + ST_A + brow0 * SB_ROWB + bco0 * 16; \
        CP16(d, ga); \
        ga = Bhi + (long long)((kt) * 32 + brow1) * LDB + bn + bco1 * 8; \
        d = sb + ST_A + brow1 * SB_ROWB + bco1 * 16; \
        CP16(d, ga); \
    } while (0)

    float acc[4][4][4];
    #pragma unroll
    for (int i = 0; i < 4; ++i)
        #pragma unroll
        for (int j = 0; j < 4; ++j)
            #pragma unroll
            for (int r = 0; r < 4; ++r) acc[i][j][r] = 0.f;

    constexpr int NK = KTOT / 32;
    ISSUE(0, 0); CP_COMMIT();
    ISSUE(1, 1); CP_COMMIT();

    int s = 0;
    #pragma unroll 1
    for (int t = 0; t < NK; ++t) {
        CP_WAIT1();
        __syncthreads();

        if (t + 2 < NK) {
            int s2 = s + 2; if (s2 >= NSTAGE) s2 -= NSTAGE;
            ISSUE(s2, t + 2);
        }
        CP_COMMIT();

        const uint32_t aB = smem_u + s * STAGE_B;
        const uint32_t bB = aB + ST_A;
        #pragma unroll
        for (int ks = 0; ks < 2; ++ks) {
            const int k0 = ks * 16;
            uint32_t ah[4][4], al[4][4], bh[2][4];
            #pragma unroll
            for (int i = 0; i < 4; ++i) {
                const int row = wm + 16 * i + (sub & 1) * 8 + lr;
                const int col = k0 + (sub >> 1) * 8;
                const uint32_t ab = aB + (uint32_t)row * SA_ROWB + (uint32_t)col * 2;
                ldsm_x4(ah[i][0], ah[i][1], ah[i][2], ah[i][3], ab);
                if constexpr (SPLIT_A) {
                    ldsm_x4(al[i][0], al[i][1], al[i][2], al[i][3], ab + SA_PLANE);
                }
            }
            #pragma unroll
            for (int jj = 0; jj < 2; ++jj) {
                const int krow = k0 + (sub & 1) * 8 + lr;
                const int ncol = wn + 16 * jj + (sub >> 1) * 8;
                const uint32_t bb = bB + (uint32_t)krow * SB_ROWB + (uint32_t)ncol * 2;
                ldsm_x4_t(bh[jj][0], bh[jj][1], bh[jj][2], bh[jj][3], bb);
            }
            #pragma unroll
            for (int i = 0; i < 4; ++i)
                #pragma unroll
                for (int j = 0; j < 4; ++j) {
                    const uint32_t* bfh = &bh[j >> 1][(j & 1) * 2];
                    mma16816(acc[i][j], ah[i], bfh);
                    if constexpr (SPLIT_A) {
                        mma16816(acc[i][j], al[i], bfh);
                    }
                }
        }
        if (++s >= NSTAGE) s -= NSTAGE;
    }

    // epilogue
    const int g  = lane >> 2;
    const int tq = lane & 3;
    #pragma unroll
    for (int i = 0; i < 4; ++i)
        #pragma unroll
        for (int half = 0; half < 2; ++half) {
            const int row = wm + 16 * i + g + 8 * half;
            const long long rb = (long long)row * LDC + bn + wn + 2 * tq;
            #pragma unroll
            for (int j = 0; j < 4; ++j) {
                const float v0 = acc[i][j][2 * half];
                const float v1 = acc[i][j][2 * half + 1];
                if constexpr (SPLIT_OUT) {
                    __half h0, h1, l0, l1;
                    split1(v0, h0, l0); split1(v1, h1, l1);
                    *(uint32_t*)(Chi + rb + 8 * j) = pack2(h0, h1);
                    *(uint32_t*)(Clo + rb + 8 * j) = pack2(l0, l1);
                } else {
                    *(float2*)(Cf + rb + 8 * j) = make_float2(v0, v1);
                }
            }
        }
    #undef ISSUE
}

// K12 merged: y in [0,3): k = w_k @ x; y in [3,6): q = w_q @ query
__global__ __launch_bounds__(256, 2)
void k12_kernel()
{
    const long long z = blockIdx.z;
    if (blockIdx.y < 3) {
        const long long my = blockIdx.y;
        gemm_body<384, HW, HW, false, true>(
            g_wkh + my * 128 * 384, nullptr,
            g_xh + z * C * HW,
            nullptr,
            g_kh + z * C * HW + my * 128 * HW,
            g_kl + z * C * HW + my * 128 * HW);
    } else {
        const long long my = blockIdx.y - 3;
        gemm_body<192, HW, HW, false, true>(
            g_wqh + my * 128 * 192, nullptr,
            g_yh + z * QC * HW,
            nullptr,
            g_qh + z * C * HW + my * 128 * HW,
            g_ql + z * C * HW + my * 128 * HW);
    }
}
__global__ __launch_bounds__(256, 2)
void kw2_kernel()  // W2 = W_eff(hi+lo) @ w_v(hi)
{
    const long long z = blockIdx.z;
    const long long my = blockIdx.y;
    gemm_body<384, 384, 384, true, true>(
        g_weffh + z * C * C + my * 128 * C,
        g_weffl + z * C * C + my * 128 * C,
        g_wvh,
        nullptr,
        g_w2h + z * C * C + my * 128 * C,
        g_w2l + z * C * C + my * 128 * C);
}
__global__ __launch_bounds__(256, 2)
void k5_kernel(float* __restrict__ out)   // out = W2(hi+lo) @ x(hi)
{
    const long long z = blockIdx.z;
    const long long my = blockIdx.y;
    gemm_body<384, HW, HW, true, false>(
        g_w2h + z * C * C + my * 128 * C,
        g_w2l + z * C * C + my * 128 * C,
        g_xh + z * C * HW,
        out + z * C * HW + my * 128 * HW,
        nullptr, nullptr);
}

// ---------------- K3: Gram partials (4-way split over n) -------------------
__global__ __launch_bounds__(256)
void gram_kernel()
{
    const int bh = blockIdx.x;          // 0..127
    const int nq = blockIdx.y;          // 0..3
    const int b = bh >> 3, h = bh & 7;
    const long long qbase = ((long long)b * C + h * DC) * HW;
    const long long kbase = ((long long)b * C + h * DC) * HW;

    __shared__ float qs[DC][65];
    __shared__ float ks[DC][65];

    const int tid = threadIdx.x;
    const int tx = tid & 15, ty = tid >> 4;

    float acc[3][3] = {};
    float nrm = 0.f;

    const int nbeg = nq * (HW / 4), nend = nbeg + (HW / 4);
    for (int n0 = nbeg; n0 < nend; n0 += 64) {
        for (int idx = tid; idx < DC * 16; idx += 256) {
            const int c = idx >> 4, nn4 = (idx & 15) << 2;
            float4 v = load4_split(g_qh, g_ql, qbase + (long long)c * HW + n0 + nn4);
            qs[c][nn4 + 0] = v.x; qs[c][nn4 + 1] = v.y; qs[c][nn4 + 2] = v.z; qs[c][nn4 + 3] = v.w;
            float4 w = load4_split(g_kh, g_kl, kbase + (long long)c * HW + n0 + nn4);
            ks[c][nn4 + 0] = w.x; ks[c][nn4 + 1] = w.y; ks[c][nn4 + 2] = w.z; ks[c][nn4 + 3] = w.w;
        }
        __syncthreads();
        #pragma unroll 4
        for (int nn = 0; nn < 64; ++nn) {
            const float a0 = qs[ty * 3 + 0][nn];
            const float a1 = qs[ty * 3 + 1][nn];
            const float a2 = qs[ty * 3 + 2][nn];
            const float b0 = ks[tx * 3 + 0][nn];
            const float b1 = ks[tx * 3 + 1][nn];
            const float b2 = ks[tx * 3 + 2][nn];
            acc[0][0] += a0 * b0; acc[0][1] += a0 * b1; acc[0][2] += a0 * b2;
            acc[1][0] += a1 * b0; acc[1][1] += a1 * b1; acc[1][2] += a1 * b2;
            acc[2][0] += a2 * b0; acc[2][1] += a2 * b1; acc[2][2] += a2 * b2;
        }
        if (tid < 96) {
            const float* row = (tid < DC) ? &qs[tid][0] : &ks[tid - DC][0];
            #pragma unroll 8
            for (int nn = 0; nn < 64; ++nn) { const float v = row[nn]; nrm += v * v; }
        }
        __syncthreads();
    }

    float* Sb = g_Sp + ((long long)nq * (B * HD) + bh) * DC * DC;
    #pragma unroll
    for (int i = 0; i < 3; i++)
        #pragma unroll
        for (int j = 0; j < 3; j++)
            Sb[(ty * 3 + i) * DC + (tx * 3 + j)] = acc[i][j];

    if (tid < DC)          g_qssp[nq * B * C + b * C + h * DC + tid]      = nrm;
    else if (tid < 2 * DC) g_kssp[nq * B * C + b * C + h * DC + tid - DC] = nrm;
}

// ---------------- K4a: softmax with folded L2 norms ------------------------
__global__ __launch_bounds__(64)
void k4a_softmax(const float* __restrict__ temp)
{
    const int bh = blockIdx.x;
    const int b = bh >> 3, h = bh & 7;
    const int tid = threadIdx.x;
    __shared__ float kinv[DC];

    if (tid < DC) {
        float kss = 0.f;
        #pragma unroll
        for (int p = 0; p < 4; ++p) kss += g_kssp[p * B * C + b * C + h * DC + tid];
        kinv[tid] = 1.f / fmaxf(sqrtf(kss), 1e-12f);
    }
    __syncthreads();

    if (tid < DC) {
        const int c = tid;
        float qss = 0.f;
        #pragma unroll
        for (int p = 0; p < 4; ++p) qss += g_qssp[p * B * C + b * C + h * DC + c];
        const float qinv = 1.f / fmaxf(sqrtf(qss), 1e-12f);
        const float T = temp[h];
        float vals[DC];
        float m = -INFINITY;
        #pragma unroll
        for (int d = 0; d < DC; d++) {
            float sv = 0.f;
            #pragma unroll
            for (int p = 0; p < 4; ++p)
                sv += g_Sp[((long long)p * (B * HD) + bh) * DC * DC + c * DC + d];
            const float l = sv * qinv * kinv[d] * T;
            vals[d] = l;
            m = fmaxf(m, l);
        }
        float ssum = 0.f;
        #pragma unroll
        for (int d = 0; d < DC; d++) { const float e = expf(vals[d] - m); vals[d] = e; ssum += e; }
        const float inv = 1.f / ssum;
        float* dst = g_attn + (long long)bh * DC * DC + c * DC;
        #pragma unroll
        for (int d = 0; d < DC; d++) dst[d] = vals[d] * inv;
    }
}

// ---------------- K4b: W_eff (split fp16 out) ------------------------------
__global__ __launch_bounds__(256)
void k4b_weff(const float* __restrict__ w_proj)
{
    const int og = blockIdx.x;   // 0..3, 96 output rows each
    const int b  = blockIdx.y;   // 0..15
    const int tid = threadIdx.x;
    __shared__ float attn_s[DC][DC + 1];
    __shared__ float w_s[96][DC];

    for (int h = 0; h < HD; ++h) {
        const float* a_src = g_attn + ((long long)(b * HD + h)) * DC * DC;
        for (int idx = tid; idx < DC * DC; idx += 256)
            attn_s[idx / DC][idx % DC] = a_src[idx];
        for (int idx = tid; idx < 96 * DC; idx += 256) {
            const int o = idx / DC, c = idx % DC;
            w_s[o][c] = w_proj[(long long)(og * 96 + o) * C + h * DC + c];
        }
        __syncthreads();
        for (int idx = tid; idx < 96 * DC; idx += 256) {
            const int o = idx / DC, d = idx % DC;
            float s = 0.f;
            #pragma unroll
            for (int c = 0; c < DC; ++c) s += w_s[o][c] * attn_s[c][d];
            const long long di = (long long)b * C * C + (long long)(og * 96 + o) * C + h * DC + d;
            __half hi, lo;
            split1(s, hi, lo);
            g_weffh[di] = hi;
            g_weffl[di] = lo;
        }
        __syncthreads();
    }
}

// ---------------- launch ---------------------------------------------------
extern "C" void kernel_launch(void* const* d_in, const int* in_sizes, int n_in,
                              void* d_out, int out_size)
{
    const float* x      = (const float*)d_in[0];
    const float* query  = (const float*)d_in[1];
    const float* w_kv   = (const float*)d_in[2];
    const float* w_q    = (const float*)d_in[3];
    const float* w_proj = (const float*)d_in[4];
    const float* temp   = (const float*)d_in[5];
    float* out = (float*)d_out;

    cudaFuncSetAttribute(k12_kernel, cudaFuncAttributeMaxDynamicSharedMemorySize, SMEM_BYTES);
    cudaFuncSetAttribute(kw2_kernel, cudaFuncAttributeMaxDynamicSharedMemorySize, SMEM_BYTES);
    cudaFuncSetAttribute(k5_kernel,  cudaFuncAttributeMaxDynamicSharedMemorySize, SMEM_BYTES);

    conv_all<<<(CONV_TOT + 255) / 256, 256>>>(x, query, w_kv, w_q);
    k12_kernel<<<dim3(HW / 128, 6, B), 256, SMEM_BYTES>>>();
    gram_kernel<<<dim3(B * HD, 4), 256>>>();
    k4a_softmax<<<B * HD, 64>>>(temp);
    k4b_weff<<<dim3(4, B), 256>>>(w_proj);
    kw2_kernel<<<dim3(3, 3, B), 256, SMEM_BYTES>>>();
    k5_kernel<<<dim3(HW / 128, 3, B), 256, SMEM_BYTES>>>(out);
}

// round 12
// speedup vs baseline: 3.8681x; 1.1881x over previous
#include <cuda_runtime.h>
#include <cuda_fp16.h>
#include <math.h>
#include <cstdint>

// ============================================================================
// CrossAttention — all-1-term fp16 mma.sync pipeline.
//
//  conv_all: x,query,w_k,w_v,w_q -> fp16 (single plane)
//  K12: k = w_k @ x; q = w_q @ query   -> fp16          [merged, mma.sync]
//  K3: Gram S = q.k^T (fp16 in, fp32 acc), 4-way split-n [SIMT]
//  K4a: softmax (L2-norm folded)                         [SIMT]
//  K4b: W_eff = w_proj_blockdiag @ attn -> fp16          [SIMT]
//  KW2: W2 = W_eff @ w_v -> fp16                         [mma.sync]
//  K5: out = W2 @ x -> fp32                              [mma.sync]
//
// Error budget (calibrated R8-R11: each direct-path fp16 rounding ~2.1e-4
// RSS): direct path now x + w_v + W_eff + W2 = 4 roundings -> ~4.2e-4.
// Normalized softmax path absorbs k/q roundings (measured: no effect).
// ============================================================================

#define B   16
#define C   384
#define QC  192
#define HD  8
#define DC  48
#define HW  4096

// ---------------- scratch (fp16 planes) ------------------------------------
__device__ __half g_xh [(long long)B * C * HW];
__device__ __half g_yh [(long long)B * QC * HW];
__device__ __half g_kh [(long long)B * C * HW];
__device__ __half g_qh [(long long)B * C * HW];
__device__ __half g_wkh[384 * 384];
__device__ __half g_wvh[384 * 384];
__device__ __half g_wqh[384 * 192];
__device__ __half g_weffh[(long long)B * C * C];
__device__ __half g_w2h[(long long)B * C * C];
__device__ float g_Sp  [4 * B * HD * DC * DC];
__device__ float g_qssp[4 * B * C];
__device__ float g_kssp[4 * B * C];
__device__ float g_attn[(long long)B * HD * DC * DC];

// ---------------- helpers --------------------------------------------------
__device__ __forceinline__ uint32_t smem_u32(const void* p) {
    uint32_t a;
    asm("{ .reg .u64 t; cvta.to.shared.u64 t, %1; cvt.u32.u64 %0, t; }" : "=r"(a) : "l"(p));
    return a;
}
__device__ __forceinline__ void ldsm_x4(uint32_t& r0, uint32_t& r1, uint32_t& r2, uint32_t& r3,
                                        uint32_t addr) {
    asm volatile("ldmatrix.sync.aligned.m8n8.x4.shared.b16 {%0,%1,%2,%3}, [%4];"
                 : "=r"(r0), "=r"(r1), "=r"(r2), "=r"(r3) : "r"(addr));
}
__device__ __forceinline__ void ldsm_x4_t(uint32_t& r0, uint32_t& r1, uint32_t& r2, uint32_t& r3,
                                          uint32_t addr) {
    asm volatile("ldmatrix.sync.aligned.m8n8.x4.trans.shared.b16 {%0,%1,%2,%3}, [%4];"
                 : "=r"(r0), "=r"(r1), "=r"(r2), "=r"(r3) : "r"(addr));
}
__device__ __forceinline__ void mma16816(float* c, const uint32_t* a, const uint32_t* b) {
    asm volatile("mma.sync.aligned.m16n8k16.row.col.f32.f16.f16.f32 "
                 "{%0,%1,%2,%3}, {%4,%5,%6,%7}, {%8,%9}, {%0,%1,%2,%3};"
                 : "+f"(c[0]), "+f"(c[1]), "+f"(c[2]), "+f"(c[3])
                 : "r"(a[0]), "r"(a[1]), "r"(a[2]), "r"(a[3]), "r"(b[0]), "r"(b[1]));
}
#define CP16(dst, src) \
    asm volatile("cp.async.cg.shared.global [%0], [%1], 16;" :: "r"(dst), "l"(src))
#define CP_COMMIT() asm volatile("cp.async.commit_group;")
#define CP_WAIT1()  asm volatile("cp.async.wait_group 1;")

__device__ __forceinline__ uint32_t pack2(__half a, __half b) {
    return (uint32_t)__half_as_ushort(a) | ((uint32_t)__half_as_ushort(b) << 16);
}
__device__ __forceinline__ float4 load4_h(const __half* hp, long long idx) {
    uint2 h = *(const uint2*)(hp + idx);
    const __half2 h0 = *reinterpret_cast<__half2*>(&h.x);
    const __half2 h1 = *reinterpret_cast<__half2*>(&h.y);
    float4 r;
    r.x = __half2float(h0.x);
    r.y = __half2float(h0.y);
    r.z = __half2float(h1.x);
    r.w = __half2float(h1.y);
    return r;
}

// ---------------- merged conversion kernel ---------------------------------
// float4-unit segments:
//  [0, 6291456)                x      -> g_xh
//  [6291456, 9437184)          query  -> g_yh
//  [9437184, 9474048)          w_k    -> g_wkh
//  [9474048, 9510912)          w_v    -> g_wvh
//  [9510912, 9529344)          w_q    -> g_wqh
#define CONV_TOT 9529344
__global__ __launch_bounds__(256)
void conv_all(const float* __restrict__ x, const float* __restrict__ query,
              const float* __restrict__ w_kv, const float* __restrict__ w_q)
{
    const long long i = (long long)blockIdx.x * 256 + threadIdx.x;
    if (i >= CONV_TOT) return;
    const float4* src;
    __half* dst;
    long long j;
    if (i < 6291456) {
        j = i; src = (const float4*)x; dst = g_xh;
    } else if (i < 9437184) {
        j = i - 6291456; src = (const float4*)query; dst = g_yh;
    } else if (i < 9474048) {
        j = i - 9437184; src = (const float4*)w_kv; dst = g_wkh;
    } else if (i < 9510912) {
        j = i - 9474048; src = (const float4*)w_kv + 36864; dst = g_wvh;
    } else {
        j = i - 9510912; src = (const float4*)w_q; dst = g_wqh;
    }
    float4 v = src[j];
    ((uint2*)dst)[j] = make_uint2(pack2(__float2half_rn(v.x), __float2half_rn(v.y)),
                                  pack2(__float2half_rn(v.z), __float2half_rn(v.w)));
}

// ---------------- GEMM geometry -------------------------------------------
// CTA 128x128, BK=32, 256 threads = 8 warps (2x4), warp tile 64x32.
// smem per stage: A plane (128 x 80B) = 10240 B; B plane (32 x 272B)
// = 8704 B; stage = 18944 B, 3 stages = 56832 B. 2 CTAs/SM.
#define SA_ROWB  80
#define SB_ROWB  272
#define ST_A     10240
#define STAGE_B  18944
#define NSTAGE   3
#define SMEM_BYTES (STAGE_B * NSTAGE)

template<int KTOT, int LDB, int LDC, bool HALF_OUT>
__device__ __forceinline__
void gemm_body(const __half* __restrict__ Ahi, const __half* __restrict__ Bhi,
               float* __restrict__ Cf, __half* __restrict__ Ch)
{
    extern __shared__ char sm[];
    const uint32_t smem_u = smem_u32(sm);

    const int tid  = threadIdx.x;
    const int wid  = tid >> 5;
    const int lane = tid & 31;
    const int bn   = blockIdx.x * 128;
    const int wm = (wid >> 2) * 64;
    const int wn = (wid & 3) * 32;
    const int sub = lane >> 3;
    const int lr  = lane & 7;

    const int ca0 = tid << 1;
    const int arow0 = ca0 >> 2,       aco0 = ca0 & 3;
    const int arow1 = (ca0 + 1) >> 2, aco1 = (ca0 + 1) & 3;
    const int brow0 = ca0 >> 4,       bco0 = ca0 & 15;
    const int brow1 = (ca0 + 1) >> 4, bco1 = (ca0 + 1) & 15;

    #define ISSUE(s, kt) do { \
        const uint32_t sb = smem_u + (s) * STAGE_B; \
        const __half* ga; uint32_t d; \
        ga = Ahi + arow0 * KTOT + (kt) * 32 + aco0 * 8; \
        d = sb + arow0 * SA_ROWB + aco0 * 16; \
        CP16(d, ga); \
        ga = Ahi + arow1 * KTOT + (kt) * 32 + aco1 * 8; \
        d = sb + arow1 * SA_ROWB + aco1 * 16; \
        CP16(d, ga); \
        ga = Bhi + (long long)((kt) * 32 + brow0) * LDB + bn + bco0 * 8; \
        d = sb + ST_A + brow0 * SB_ROWB + bco0 * 16; \
        CP16(d, ga); \
        ga = Bhi + (long long)((kt) * 32 + brow1) * LDB + bn + bco1 * 8; \
        d = sb + ST_A + brow1 * SB_ROWB + bco1 * 16; \
        CP16(d, ga); \
    } while (0)

    float acc[4][4][4];
    #pragma unroll
    for (int i = 0; i < 4; ++i)
        #pragma unroll
        for (int j = 0; j < 4; ++j)
            #pragma unroll
            for (int r = 0; r < 4; ++r) acc[i][j][r] = 0.f;

    constexpr int NK = KTOT / 32;
    ISSUE(0, 0); CP_COMMIT();
    ISSUE(1, 1); CP_COMMIT();

    int s = 0;
    #pragma unroll 1
    for (int t = 0; t < NK; ++t) {
        CP_WAIT1();
        __syncthreads();

        if (t + 2 < NK) {
            int s2 = s + 2; if (s2 >= NSTAGE) s2 -= NSTAGE;
            ISSUE(s2, t + 2);
        }
        CP_COMMIT();

        const uint32_t aB = smem_u + s * STAGE_B;
        const uint32_t bB = aB + ST_A;
        #pragma unroll
        for (int ks = 0; ks < 2; ++ks) {
            const int k0 = ks * 16;
            uint32_t ah[4][4], bh[2][4];
            #pragma unroll
            for (int i = 0; i < 4; ++i) {
                const int row = wm + 16 * i + (sub & 1) * 8 + lr;
                const int col = k0 + (sub >> 1) * 8;
                const uint32_t ab = aB + (uint32_t)row * SA_ROWB + (uint32_t)col * 2;
                ldsm_x4(ah[i][0], ah[i][1], ah[i][2], ah[i][3], ab);
            }
            #pragma unroll
            for (int jj = 0; jj < 2; ++jj) {
                const int krow = k0 + (sub & 1) * 8 + lr;
                const int ncol = wn + 16 * jj + (sub >> 1) * 8;
                const uint32_t bb = bB + (uint32_t)krow * SB_ROWB + (uint32_t)ncol * 2;
                ldsm_x4_t(bh[jj][0], bh[jj][1], bh[jj][2], bh[jj][3], bb);
            }
            #pragma unroll
            for (int i = 0; i < 4; ++i)
                #pragma unroll
                for (int j = 0; j < 4; ++j)
                    mma16816(acc[i][j], ah[i], &bh[j >> 1][(j & 1) * 2]);
        }
        if (++s >= NSTAGE) s -= NSTAGE;
    }

    // epilogue
    const int g  = lane >> 2;
    const int tq = lane & 3;
    #pragma unroll
    for (int i = 0; i < 4; ++i)
        #pragma unroll
        for (int half = 0; half < 2; ++half) {
            const int row = wm + 16 * i + g + 8 * half;
            const long long rb = (long long)row * LDC + bn + wn + 2 * tq;
            #pragma unroll
            for (int j = 0; j < 4; ++j) {
                const float v0 = acc[i][j][2 * half];
                const float v1 = acc[i][j][2 * half + 1];
                if constexpr (HALF_OUT) {
                    *(uint32_t*)(Ch + rb + 8 * j) =
                        pack2(__float2half_rn(v0), __float2half_rn(v1));
                } else {
                    *(float2*)(Cf + rb + 8 * j) = make_float2(v0, v1);
                }
            }
        }
    #undef ISSUE
}

// K12 merged: y in [0,3): k = w_k @ x; y in [3,6): q = w_q @ query
__global__ __launch_bounds__(256, 2)
void k12_kernel()
{
    const long long z = blockIdx.z;
    if (blockIdx.y < 3) {
        const long long my = blockIdx.y;
        gemm_body<384, HW, HW, true>(
            g_wkh + my * 128 * 384,
            g_xh + z * C * HW,
            nullptr,
            g_kh + z * C * HW + my * 128 * HW);
    } else {
        const long long my = blockIdx.y - 3;
        gemm_body<192, HW, HW, true>(
            g_wqh + my * 128 * 192,
            g_yh + z * QC * HW,
            nullptr,
            g_qh + z * C * HW + my * 128 * HW);
    }
}
__global__ __launch_bounds__(256, 2)
void kw2_kernel()  // W2 = W_eff @ w_v
{
    const long long z = blockIdx.z;
    const long long my = blockIdx.y;
    gemm_body<384, 384, 384, true>(
        g_weffh + z * C * C + my * 128 * C,
        g_wvh,
        nullptr,
        g_w2h + z * C * C + my * 128 * C);
}
__global__ __launch_bounds__(256, 2)
void k5_kernel(float* __restrict__ out)   // out = W2 @ x
{
    const long long z = blockIdx.z;
    const long long my = blockIdx.y;
    gemm_body<384, HW, HW, false>(
        g_w2h + z * C * C + my * 128 * C,
        g_xh + z * C * HW,
        out + z * C * HW + my * 128 * HW,
        nullptr);
}

// ---------------- K3: Gram partials (4-way split over n) -------------------
__global__ __launch_bounds__(256)
void gram_kernel()
{
    const int bh = blockIdx.x;          // 0..127
    const int nq = blockIdx.y;          // 0..3
    const int b = bh >> 3, h = bh & 7;
    const long long base = ((long long)b * C + h * DC) * HW;

    __shared__ float qs[DC][65];
    __shared__ float ks[DC][65];

    const int tid = threadIdx.x;
    const int tx = tid & 15, ty = tid >> 4;

    float acc[3][3] = {};
    float nrm = 0.f;

    const int nbeg = nq * (HW / 4), nend = nbeg + (HW / 4);
    for (int n0 = nbeg; n0 < nend; n0 += 64) {
        for (int idx = tid; idx < DC * 16; idx += 256) {
            const int c = idx >> 4, nn4 = (idx & 15) << 2;
            float4 v = load4_h(g_qh, base + (long long)c * HW + n0 + nn4);
            qs[c][nn4 + 0] = v.x; qs[c][nn4 + 1] = v.y; qs[c][nn4 + 2] = v.z; qs[c][nn4 + 3] = v.w;
            float4 w = load4_h(g_kh, base + (long long)c * HW + n0 + nn4);
            ks[c][nn4 + 0] = w.x; ks[c][nn4 + 1] = w.y; ks[c][nn4 + 2] = w.z; ks[c][nn4 + 3] = w.w;
        }
        __syncthreads();
        #pragma unroll 4
        for (int nn = 0; nn < 64; ++nn) {
            const float a0 = qs[ty * 3 + 0][nn];
            const float a1 = qs[ty * 3 + 1][nn];
            const float a2 = qs[ty * 3 + 2][nn];
            const float b0 = ks[tx * 3 + 0][nn];
            const float b1 = ks[tx * 3 + 1][nn];
            const float b2 = ks[tx * 3 + 2][nn];
            acc[0][0] += a0 * b0; acc[0][1] += a0 * b1; acc[0][2] += a0 * b2;
            acc[1][0] += a1 * b0; acc[1][1] += a1 * b1; acc[1][2] += a1 * b2;
            acc[2][0] += a2 * b0; acc[2][1] += a2 * b1; acc[2][2] += a2 * b2;
        }
        if (tid < 96) {
            const float* row = (tid < DC) ? &qs[tid][0] : &ks[tid - DC][0];
            #pragma unroll 8
            for (int nn = 0; nn < 64; ++nn) { const float v = row[nn]; nrm += v * v; }
        }
        __syncthreads();
    }

    float* Sb = g_Sp + ((long long)nq * (B * HD) + bh) * DC * DC;
    #pragma unroll
    for (int i = 0; i < 3; i++)
        #pragma unroll
        for (int j = 0; j < 3; j++)
            Sb[(ty * 3 + i) * DC + (tx * 3 + j)] = acc[i][j];

    if (tid < DC)          g_qssp[nq * B * C + b * C + h * DC + tid]      = nrm;
    else if (tid < 2 * DC) g_kssp[nq * B * C + b * C + h * DC + tid - DC] = nrm;
}

// ---------------- K4a: softmax with folded L2 norms ------------------------
__global__ __launch_bounds__(64)
void k4a_softmax(const float* __restrict__ temp)
{
    const int bh = blockIdx.x;
    const int b = bh >> 3, h = bh & 7;
    const int tid = threadIdx.x;
    __shared__ float kinv[DC];

    if (tid < DC) {
        float kss = 0.f;
        #pragma unroll
        for (int p = 0; p < 4; ++p) kss += g_kssp[p * B * C + b * C + h * DC + tid];
        kinv[tid] = 1.f / fmaxf(sqrtf(kss), 1e-12f);
    }
    __syncthreads();

    if (tid < DC) {
        const int c = tid;
        float qss = 0.f;
        #pragma unroll
        for (int p = 0; p < 4; ++p) qss += g_qssp[p * B * C + b * C + h * DC + c];
        const float qinv = 1.f / fmaxf(sqrtf(qss), 1e-12f);
        const float T = temp[h];
        float vals[DC];
        float m = -INFINITY;
        #pragma unroll
        for (int d = 0; d < DC; d++) {
            float sv = 0.f;
            #pragma unroll
            for (int p = 0; p < 4; ++p)
                sv += g_Sp[((long long)p * (B * HD) + bh) * DC * DC + c * DC + d];
            const float l = sv * qinv * kinv[d] * T;
            vals[d] = l;
            m = fmaxf(m, l);
        }
        float ssum = 0.f;
        #pragma unroll
        for (int d = 0; d < DC; d++) { const float e = expf(vals[d] - m); vals[d] = e; ssum += e; }
        const float inv = 1.f / ssum;
        float* dst = g_attn + (long long)bh * DC * DC + c * DC;
        #pragma unroll
        for (int d = 0; d < DC; d++) dst[d] = vals[d] * inv;
    }
}

// ---------------- K4b: W_eff (fp16 out) ------------------------------------
__global__ __launch_bounds__(256)
void k4b_weff(const float* __restrict__ w_proj)
{
    const int og = blockIdx.x;   // 0..3, 96 output rows each
    const int b  = blockIdx.y;   // 0..15
    const int tid = threadIdx.x;
    __shared__ float attn_s[DC][DC + 1];
    __shared__ float w_s[96][DC];

    for (int h = 0; h < HD; ++h) {
        const float* a_src = g_attn + ((long long)(b * HD + h)) * DC * DC;
        for (int idx = tid; idx < DC * DC; idx += 256)
            attn_s[idx / DC][idx % DC] = a_src[idx];
        for (int idx = tid; idx < 96 * DC; idx += 256) {
            const int o = idx / DC, c = idx % DC;
            w_s[o][c] = w_proj[(long long)(og * 96 + o) * C + h * DC + c];
        }
        __syncthreads();
        for (int idx = tid; idx < 96 * DC; idx += 256) {
            const int o = idx / DC, d = idx % DC;
            float s = 0.f;
            #pragma unroll
            for (int c = 0; c < DC; ++c) s += w_s[o][c] * attn_s[c][d];
            g_weffh[(long long)b * C * C + (long long)(og * 96 + o) * C + h * DC + d] =
                __float2half_rn(s);
        }
        __syncthreads();
    }
}

// ---------------- launch ---------------------------------------------------
extern "C" void kernel_launch(void* const* d_in, const int* in_sizes, int n_in,
                              void* d_out, int out_size)
{
    const float* x      = (const float*)d_in[0];
    const float* query  = (const float*)d_in[1];
    const float* w_kv   = (const float*)d_in[2];
    const float* w_q    = (const float*)d_in[3];
    const float* w_proj = (const float*)d_in[4];
    const float* temp   = (const float*)d_in[5];
    float* out = (float*)d_out;

    cudaFuncSetAttribute(k12_kernel, cudaFuncAttributeMaxDynamicSharedMemorySize, SMEM_BYTES);
    cudaFuncSetAttribute(kw2_kernel, cudaFuncAttributeMaxDynamicSharedMemorySize, SMEM_BYTES);
    cudaFuncSetAttribute(k5_kernel,  cudaFuncAttributeMaxDynamicSharedMemorySize, SMEM_BYTES);

    conv_all<<<(CONV_TOT + 255) / 256, 256>>>(x, query, w_kv, w_q);
    k12_kernel<<<dim3(HW / 128, 6, B), 256, SMEM_BYTES>>>();
    gram_kernel<<<dim3(B * HD, 4), 256>>>();
    k4a_softmax<<<B * HD, 64>>>(temp);
    k4b_weff<<<dim3(4, B), 256>>>(w_proj);
    kw2_kernel<<<dim3(3, 3, B), 256, SMEM_BYTES>>>();
    k5_kernel<<<dim3(HW / 128, 3, B), 256, SMEM_BYTES>>>(out);
}